// round 10
// baseline (speedup 1.0000x reference)
#include <cuda_runtime.h>
#include <cuda_fp16.h>
#include <math.h>
#include <cstdint>

#define N_NODES 100000
#define E_EDGES 800000
#define D 128
#define EPSV 1e-4f
#define LN_EPSV 1e-5f

#define SCAN_B 512
#define NBLK ((N_NODES + SCAN_B - 1) / SCAN_B)   // 196

#define TILE_M 256
#define MM_CTAS ((N_NODES + TILE_M - 1) / TILE_M)  // 391
#define MM_THREADS 512

// ---- scratch (device globals; no allocation allowed) ----
__device__ float  g_rate[(size_t)N_NODES * D];
__device__ float  g_gamma[(size_t)N_NODES * D];
__device__ float  g_xa[(size_t)N_NODES * D];    // cnt*x[i] + sum x[col]
__device__ float  g_agg[(size_t)N_NODES * D];   // xa @ W_fc
__device__ int    g_cnt[N_NODES];
__device__ int    g_cur[N_NODES];
__device__ int    g_off[N_NODES];
__device__ int    g_bsum[NBLK];
__device__ int    g_ecol[E_EDGES];
// fp16-split, transposed weights: [mat(3)][hi/lo(2)][n(128)][k(128)] halves
// mat order: 0 = W_rate, 1 = W_rob, 2 = W_fc
__device__ __half g_wh[3 * 2 * 128 * 128];

// ============================ helpers ============================
__device__ __forceinline__ uint32_t smem_u32(const void* p) {
    uint32_t a;
    asm("{ .reg .u64 t; cvta.to.shared.u64 t, %1; cvt.u32.u64 %0, t; }" : "=r"(a) : "l"(p));
    return a;
}

__device__ __forceinline__ void ldmatrix4(uint32_t* r, uint32_t addr) {
    asm volatile("ldmatrix.sync.aligned.m8n8.x4.shared.b16 {%0,%1,%2,%3}, [%4];"
                 : "=r"(r[0]), "=r"(r[1]), "=r"(r[2]), "=r"(r[3]) : "r"(addr));
}

__device__ __forceinline__ void mma16816(float* c, const uint32_t* a, uint32_t b0, uint32_t b1) {
    asm volatile("mma.sync.aligned.m16n8k16.row.col.f32.f16.f16.f32 "
                 "{%0,%1,%2,%3}, {%4,%5,%6,%7}, {%8,%9}, {%0,%1,%2,%3};"
                 : "+f"(c[0]), "+f"(c[1]), "+f"(c[2]), "+f"(c[3])
                 : "r"(a[0]), "r"(a[1]), "r"(a[2]), "r"(a[3]), "r"(b0), "r"(b1));
}

__device__ __forceinline__ void cp_async16(uint32_t saddr, const void* gaddr) {
    asm volatile("cp.async.cg.shared.global [%0], [%1], 16;" :: "r"(saddr), "l"(gaddr));
}
__device__ __forceinline__ void cp_commit() { asm volatile("cp.async.commit_group;"); }
__device__ __forceinline__ void cp_wait0()  { asm volatile("cp.async.wait_group 0;" ::: "memory"); }

// ============================ small kernels ============================
__global__ void k_zero() {
    int i = blockIdx.x * blockDim.x + threadIdx.x;
    if (i < N_NODES) g_cnt[i] = 0;
}

__global__ void k_count(const int* __restrict__ row) {
    int e = blockIdx.x * blockDim.x + threadIdx.x;
    if (e < E_EDGES) atomicAdd(&g_cnt[row[e]], 1);
}

__global__ __launch_bounds__(SCAN_B) void k_scan1() {
    __shared__ int wsum[SCAN_B / 32];
    int i = blockIdx.x * SCAN_B + threadIdx.x;
    int lane = threadIdx.x & 31, wid = threadIdx.x >> 5;
    int v = (i < N_NODES) ? g_cnt[i] : 0;
    if (i < N_NODES) g_cur[i] = 0;
    int s = v;
    #pragma unroll
    for (int o = 1; o < 32; o <<= 1) { int t = __shfl_up_sync(~0u, s, o); if (lane >= o) s += t; }
    if (lane == 31) wsum[wid] = s;
    __syncthreads();
    if (wid == 0) {
        int ws = (lane < SCAN_B / 32) ? wsum[lane] : 0;
        #pragma unroll
        for (int o = 1; o < SCAN_B / 32; o <<= 1) { int t = __shfl_up_sync(~0u, ws, o); if (lane >= o) ws += t; }
        if (lane < SCAN_B / 32) wsum[lane] = ws;
    }
    __syncthreads();
    int base = (wid > 0) ? wsum[wid - 1] : 0;
    if (i < N_NODES) g_off[i] = base + s - v;
    if (threadIdx.x == SCAN_B - 1) g_bsum[blockIdx.x] = base + s;
}

__global__ __launch_bounds__(256) void k_scan2() {
    __shared__ int wsum[8];
    int lane = threadIdx.x & 31, wid = threadIdx.x >> 5;
    int v = (threadIdx.x < NBLK) ? g_bsum[threadIdx.x] : 0;
    int s = v;
    #pragma unroll
    for (int o = 1; o < 32; o <<= 1) { int t = __shfl_up_sync(~0u, s, o); if (lane >= o) s += t; }
    if (lane == 31) wsum[wid] = s;
    __syncthreads();
    if (wid == 0) {
        int ws = (lane < 8) ? wsum[lane] : 0;
        #pragma unroll
        for (int o = 1; o < 8; o <<= 1) { int t = __shfl_up_sync(~0u, ws, o); if (lane >= o) ws += t; }
        if (lane < 8) wsum[lane] = ws;
    }
    __syncthreads();
    int base = (wid > 0) ? wsum[wid - 1] : 0;
    if (threadIdx.x < NBLK) g_bsum[threadIdx.x] = base + s - v;
}

__global__ __launch_bounds__(256) void k_bin(const int* __restrict__ row, const int* __restrict__ col) {
    int e = blockIdx.x * blockDim.x + threadIdx.x;
    if (e >= E_EDGES) return;
    int r = row[e];
    int pos = g_off[r] + g_bsum[r >> 9] + atomicAdd(&g_cur[r], 1);
    g_ecol[pos] = col[e];
}

// ---- gather on the INPUT: xa[i] = cnt*x[i] + sum_{edges} x[col] ----
__global__ __launch_bounds__(256) void k_gather(const float* __restrict__ x) {
    int w = (blockIdx.x * blockDim.x + threadIdx.x) >> 5;
    int lane = threadIdx.x & 31;
    if (w >= N_NODES) return;
    size_t base = (size_t)w * D;

    int start = g_off[w] + g_bsum[w >> 9];
    int cnt = g_cnt[w];
    float fc = (float)cnt;

    float4 xs = __ldg(((const float4*)(x + base)) + lane);
    float4 acc = make_float4(fc * xs.x, fc * xs.y, fc * xs.z, fc * xs.w);

    int j = 0;
    for (; j + 4 <= cnt; j += 4) {
        int c0 = g_ecol[start + j + 0];
        int c1 = g_ecol[start + j + 1];
        int c2 = g_ecol[start + j + 2];
        int c3 = g_ecol[start + j + 3];
        float4 v0 = __ldg(((const float4*)(x + (size_t)c0 * D)) + lane);
        float4 v1 = __ldg(((const float4*)(x + (size_t)c1 * D)) + lane);
        float4 v2 = __ldg(((const float4*)(x + (size_t)c2 * D)) + lane);
        float4 v3 = __ldg(((const float4*)(x + (size_t)c3 * D)) + lane);
        acc.x += (v0.x + v1.x) + (v2.x + v3.x);
        acc.y += (v0.y + v1.y) + (v2.y + v3.y);
        acc.z += (v0.z + v1.z) + (v2.z + v3.z);
        acc.w += (v0.w + v1.w) + (v2.w + v3.w);
    }
    for (; j < cnt; j++) {
        int c = g_ecol[start + j];
        float4 v = __ldg(((const float4*)(x + (size_t)c * D)) + lane);
        acc.x += v.x; acc.y += v.y; acc.z += v.z; acc.w += v.w;
    }
    ((float4*)(g_xa + base))[lane] = acc;
}

// ---- pre-transpose + fp16-split W into g_wh[mat][hi/lo][n][k] ----
// mat order: 0=W_rate, 1=W_rob, 2=W_fc
__global__ __launch_bounds__(256) void k_wsplit(const float* __restrict__ W_rate,
                                                const float* __restrict__ W_rob,
                                                const float* __restrict__ W_fc) {
    int t = blockIdx.x * blockDim.x + threadIdx.x;   // 3*128*32 = 12288
    if (t >= 3 * 128 * 32) return;
    int mat = t >> 12;
    int n = (t & 4095) >> 5;
    int k0 = (t & 31) << 2;
    const float* W = (mat == 0) ? W_rate : ((mat == 1) ? W_rob : W_fc);
    __half hi[4], lo[4];
    #pragma unroll
    for (int i = 0; i < 4; i++) {
        float v = W[(size_t)(k0 + i) * D + n];
        __half h = __float2half_rn(v);
        hi[i] = h;
        lo[i] = __float2half_rn(v - __half2float(h));
    }
    size_t oh = ((size_t)(mat * 2 + 0) << 14) + (n << 7) + k0;
    size_t ol = ((size_t)(mat * 2 + 1) << 14) + (n << 7) + k0;
    *(uint2*)(g_wh + oh) = *(uint2*)hi;
    *(uint2*)(g_wh + ol) = *(uint2*)lo;
}

// ============================ mma.sync GEMM (generalized) ============================
// TILE_M=256, 512 threads (16 warps: 8 M-groups x 2 N-groups).
// 2-term split: in_hi * (W_hi + W_lo).
// mats [mlo, mhi): 0 -> softplus -> g_rate ; 1 -> +b_rob -> g_gamma ; 2 -> raw -> g_agg
#define SM_XHI   0
#define SM_WB    65536
#define SM_TOTAL 131072

__global__ __launch_bounds__(MM_THREADS, 1) void k_mm(const float* __restrict__ in,
                                                      int mlo, int mhi,
                                                      const float* __restrict__ b_rob) {
    extern __shared__ char smem[];
    const uint32_t sbase = smem_u32(smem);
    const int tid = threadIdx.x;
    const int wid = tid >> 5;
    const int lane = tid & 31;
    const int m0 = blockIdx.x * TILE_M;
    const int warpM = wid & 7;     // rows 32*warpM .. +32
    const int warpN = wid >> 3;    // cols 64*warpN .. +64

    // ---- prefetch W[mlo] (hi+lo, 64KB) ----
    {
        const char* wsrc = (const char*)g_wh + ((size_t)mlo << 16);
        #pragma unroll
        for (int r = 0; r < 8; r++) {
            int idx = (r << 9) + tid;           // 0..4095 16B units
            int h = idx >> 11;
            int rem = idx & 2047;
            int n = rem >> 4;
            int u = rem & 15;
            uint32_t dst = sbase + SM_WB + (h << 15) + (uint32_t)(n * 256 + ((u ^ (n & 7)) << 4));
            cp_async16(dst, wsrc + ((size_t)h << 15) + (size_t)n * 256 + (u << 4));
        }
        cp_commit();
    }

    // ---- stage input tile as fp16 hi (256 rows x 128 k) ----
    #pragma unroll
    for (int r = 0; r < 16; r++) {
        int idx = (r << 9) + tid;           // 0..8191
        int m = idx >> 5;
        int kq = idx & 31;
        float4 v = make_float4(0.f, 0.f, 0.f, 0.f);
        if (m0 + m < N_NODES) v = *(const float4*)(in + (size_t)(m0 + m) * D + (kq << 2));
        uint2 hp;
        hp.x = __half_as_ushort(__float2half_rn(v.x)) | ((uint32_t)__half_as_ushort(__float2half_rn(v.y)) << 16);
        hp.y = __half_as_ushort(__float2half_rn(v.z)) | ((uint32_t)__half_as_ushort(__float2half_rn(v.w)) << 16);
        int u = kq >> 1;
        int off8 = (kq & 1) << 3;
        uint32_t so = (uint32_t)(m * 256 + ((u ^ (m & 7)) << 4) + off8);
        *(uint2*)(smem + SM_XHI + so) = hp;
    }
    cp_wait0();
    __syncthreads();

    // per-thread ldmatrix address components
    const int rowA_off = (lane & 7) + (((lane >> 3) & 1) << 3);
    const int dA = lane >> 4;
    const int nB_off = (lane & 7) + (((lane >> 4) & 1) << 3);
    const int dB = (lane >> 3) & 1;

    int rowA[2], s7A[2];
    #pragma unroll
    for (int mt = 0; mt < 2; mt++) {
        int rr = warpM * 32 + mt * 16 + rowA_off;
        rowA[mt] = rr * 256; s7A[mt] = rr & 7;
    }
    int rowB[4], s7B[4];
    #pragma unroll
    for (int nt2 = 0; nt2 < 4; nt2++) {
        int nn = warpN * 64 + nt2 * 16 + nB_off;
        rowB[nt2] = nn * 256; s7B[nt2] = nn & 7;
    }

    const int g4 = lane >> 2;
    const int t4 = lane & 3;

    for (int mat = mlo; mat < mhi; mat++) {
        float acc[2][8][4];
        #pragma unroll
        for (int mt = 0; mt < 2; mt++)
            #pragma unroll
            for (int nt = 0; nt < 8; nt++)
                #pragma unroll
                for (int i = 0; i < 4; i++) acc[mt][nt][i] = 0.f;

        #pragma unroll 1
        for (int term = 0; term < 2; term++) {
            const uint32_t abase = sbase + SM_XHI;
            const uint32_t bbase = sbase + SM_WB + ((term == 1) ? 32768u : 0u);
            #pragma unroll 1
            for (int ks = 0; ks < 8; ks++) {
                uint32_t a[2][4];
                #pragma unroll
                for (int mt = 0; mt < 2; mt++) {
                    int u = 2 * ks + dA;
                    ldmatrix4(a[mt], abase + rowA[mt] + ((u ^ s7A[mt]) << 4));
                }
                uint32_t b[4][4];
                #pragma unroll
                for (int nt2 = 0; nt2 < 4; nt2++) {
                    int u = 2 * ks + dB;
                    ldmatrix4(b[nt2], bbase + rowB[nt2] + ((u ^ s7B[nt2]) << 4));
                }
                #pragma unroll
                for (int mt = 0; mt < 2; mt++)
                    #pragma unroll
                    for (int nt = 0; nt < 8; nt++)
                        mma16816(acc[mt][nt], a[mt], b[nt >> 1][(nt & 1) << 1], b[nt >> 1][((nt & 1) << 1) + 1]);
            }
        }

        // prefetch next W while epilogue runs
        if (mat + 1 < mhi) {
            __syncthreads();
            const char* wsrc = (const char*)g_wh + ((size_t)(mat + 1) << 16);
            #pragma unroll
            for (int r = 0; r < 8; r++) {
                int idx = (r << 9) + tid;
                int h = idx >> 11;
                int rem = idx & 2047;
                int n = rem >> 4;
                int u = rem & 15;
                uint32_t dst = sbase + SM_WB + (h << 15) + (uint32_t)(n * 256 + ((u ^ (n & 7)) << 4));
                cp_async16(dst, wsrc + ((size_t)h << 15) + (size_t)n * 256 + (u << 4));
            }
            cp_commit();
        }

        // ---- epilogue ----
        {
            float* outp = (mat == 0) ? g_rate : ((mat == 1) ? g_gamma : g_agg);
            #pragma unroll
            for (int mt = 0; mt < 2; mt++) {
                int r0 = m0 + warpM * 32 + mt * 16 + g4;
                int r1 = r0 + 8;
                #pragma unroll
                for (int nt = 0; nt < 8; nt++) {
                    int col = warpN * 64 + nt * 8 + t4 * 2;
                    float v0 = acc[mt][nt][0], v1 = acc[mt][nt][1];
                    float v2 = acc[mt][nt][2], v3 = acc[mt][nt][3];
                    if (mat == 0) {
                        v0 = ((v0 > 20.f) ? v0 : log1pf(__expf(v0))) + EPSV;
                        v1 = ((v1 > 20.f) ? v1 : log1pf(__expf(v1))) + EPSV;
                        v2 = ((v2 > 20.f) ? v2 : log1pf(__expf(v2))) + EPSV;
                        v3 = ((v3 > 20.f) ? v3 : log1pf(__expf(v3))) + EPSV;
                    } else if (mat == 1) {
                        float b0 = b_rob[col], b1 = b_rob[col + 1];
                        v0 += b0; v1 += b1; v2 += b0; v3 += b1;
                    }
                    if (r0 < N_NODES) *(float2*)(outp + (size_t)r0 * D + col) = make_float2(v0, v1);
                    if (r1 < N_NODES) *(float2*)(outp + (size_t)r1 * D + col) = make_float2(v2, v3);
                }
            }
        }

        if (mat + 1 < mhi) { cp_wait0(); __syncthreads(); }
    }
}

// ---------------- final: combine + LayerNorm (pure streaming, one warp/node) ----
__global__ __launch_bounds__(256) void k_final(const int* __restrict__ degree,
                                               const float* __restrict__ b_fc,
                                               const float* __restrict__ ln_g,
                                               const float* __restrict__ ln_b,
                                               float* __restrict__ out)
{
    int w = (blockIdx.x * blockDim.x + threadIdx.x) >> 5;
    int lane = threadIdx.x & 31;
    if (w >= N_NODES) return;
    size_t base = (size_t)w * D;

    float4 a4 = ((const float4*)(g_agg + base))[lane];
    float4 r4 = ((const float4*)(g_rate + base))[lane];
    float4 g4 = ((const float4*)(g_gamma + base))[lane];
    float4 bf = ((const float4*)b_fc)[lane];
    float fc2 = 2.0f * (float)g_cnt[w];
    float deg = (float)degree[w];

    float y[4];
    {
        const float* ap = (const float*)&a4;
        const float* rp = (const float*)&r4;
        const float* gp = (const float*)&g4;
        const float* bp = (const float*)&bf;
        #pragma unroll
        for (int i = 0; i < 4; i++) {
            float agg_full = ap[i] + fc2 * bp[i];
            y[i] = (rp[i] * agg_full + gp[i]) / (1.0f + EPSV + rp[i] * deg);
        }
    }

    float s = y[0] + y[1] + y[2] + y[3];
    float s2 = y[0]*y[0] + y[1]*y[1] + y[2]*y[2] + y[3]*y[3];
    #pragma unroll
    for (int off = 16; off > 0; off >>= 1) {
        s  += __shfl_xor_sync(0xffffffffu, s,  off);
        s2 += __shfl_xor_sync(0xffffffffu, s2, off);
    }
    float mean = s * (1.0f / D);
    float var = s2 * (1.0f / D) - mean * mean;
    float rstd = rsqrtf(var + LN_EPSV);

    float4 lg = ((const float4*)ln_g)[lane];
    float4 lb = ((const float4*)ln_b)[lane];
    float4 o;
    o.x = (y[0] - mean) * rstd * lg.x + lb.x;
    o.y = (y[1] - mean) * rstd * lg.y + lb.y;
    o.z = (y[2] - mean) * rstd * lg.z + lb.z;
    o.w = (y[3] - mean) * rstd * lg.w + lb.w;
    ((float4*)(out + base))[lane] = o;
}

// ---------------- launch ----------------
extern "C" void kernel_launch(void* const* d_in, const int* in_sizes, int n_in,
                              void* d_out, int out_size) {
    const float* x      = (const float*)d_in[0];
    const int*   ei     = (const int*)  d_in[1];
    const int*   degree = (const int*)  d_in[2];
    const float* W_fc   = (const float*)d_in[3];
    const float* b_fc   = (const float*)d_in[4];
    const float* W_rate = (const float*)d_in[5];
    const float* W_rob  = (const float*)d_in[6];
    const float* b_rob  = (const float*)d_in[7];
    const float* ln_g   = (const float*)d_in[8];
    const float* ln_b   = (const float*)d_in[9];
    float* out = (float*)d_out;

    const int* row = ei;             // edge_index[0]
    const int* col = ei + E_EDGES;   // edge_index[1]

    // one-time setup (outside capture on the first/correctness call)
    static cudaStream_t sideStream = nullptr;
    static cudaEvent_t evRoot = nullptr, evSide = nullptr;
    static float* d_xa = nullptr;
    if (!sideStream) {
        cudaStreamCreateWithFlags(&sideStream, cudaStreamNonBlocking);
        cudaEventCreateWithFlags(&evRoot, cudaEventDisableTiming);
        cudaEventCreateWithFlags(&evSide, cudaEventDisableTiming);
        cudaFuncSetAttribute(k_mm, cudaFuncAttributeMaxDynamicSharedMemorySize, SM_TOTAL);
        cudaGetSymbolAddress((void**)&d_xa, g_xa);
    }

    // fork
    cudaEventRecord(evRoot, 0);
    cudaStreamWaitEvent(sideStream, evRoot, 0);

    // side stream: CSR build + x-space gather
    k_zero<<<(N_NODES + 255) / 256, 256, 0, sideStream>>>();
    k_count<<<(E_EDGES + 255) / 256, 256, 0, sideStream>>>(row);
    k_scan1<<<NBLK, SCAN_B, 0, sideStream>>>();
    k_scan2<<<1, 256, 0, sideStream>>>();
    k_bin<<<(E_EDGES + 255) / 256, 256, 0, sideStream>>>(row, col);
    k_gather<<<(int)(((size_t)N_NODES * 32 + 255) / 256), 256, 0, sideStream>>>(x);
    cudaEventRecord(evSide, sideStream);

    // main stream: weight split + rate/gamma GEMMs (concurrent with side chain)
    k_wsplit<<<(3 * 128 * 32 + 255) / 256, 256>>>(W_rate, W_rob, W_fc);
    k_mm<<<MM_CTAS, MM_THREADS, SM_TOTAL>>>(x, 0, 2, b_rob);

    // join: xa GEMM, then streaming combine + LN
    cudaStreamWaitEvent(0, evSide, 0);
    k_mm<<<MM_CTAS, MM_THREADS, SM_TOTAL>>>(d_xa, 2, 3, b_rob);
    k_final<<<(int)(((size_t)N_NODES * 32 + 255) / 256), 256>>>(degree, b_fc, ln_g, ln_b, out);
}

// round 13
// speedup vs baseline: 1.2307x; 1.2307x over previous
#include <cuda_runtime.h>
#include <cuda_fp16.h>
#include <math.h>
#include <cstdint>

#define N_NODES 100000
#define E_EDGES 800000
#define D 128
#define EPSV 1e-4f
#define LN_EPSV 1e-5f

#define SCAN_B 512
#define NBLK ((N_NODES + SCAN_B - 1) / SCAN_B)   // 196

#define TILE_M 256
#define MM_CTAS ((N_NODES + TILE_M - 1) / TILE_M)  // 391
#define MM_THREADS 512

// ---- scratch (device globals; no allocation allowed) ----
__device__ float  g_h[(size_t)N_NODES * D];
__device__ float  g_rate[(size_t)N_NODES * D];
__device__ float  g_gamma[(size_t)N_NODES * D];
__device__ int    g_cnt[N_NODES];
__device__ int    g_cur[N_NODES];
__device__ int    g_off[N_NODES];
__device__ int    g_bsum[NBLK];
__device__ int    g_ecol[E_EDGES];
// fp16 transposed weights: [mat(3)][n(128)][k(128)] halves (32KB per mat)
__device__ __half g_wh[3 * 128 * 128];

// ============================ helpers ============================
__device__ __forceinline__ uint32_t smem_u32(const void* p) {
    uint32_t a;
    asm("{ .reg .u64 t; cvta.to.shared.u64 t, %1; cvt.u32.u64 %0, t; }" : "=r"(a) : "l"(p));
    return a;
}

__device__ __forceinline__ void ldmatrix4(uint32_t* r, uint32_t addr) {
    asm volatile("ldmatrix.sync.aligned.m8n8.x4.shared.b16 {%0,%1,%2,%3}, [%4];"
                 : "=r"(r[0]), "=r"(r[1]), "=r"(r[2]), "=r"(r[3]) : "r"(addr));
}

__device__ __forceinline__ void mma16816(float* c, const uint32_t* a, uint32_t b0, uint32_t b1) {
    asm volatile("mma.sync.aligned.m16n8k16.row.col.f32.f16.f16.f32 "
                 "{%0,%1,%2,%3}, {%4,%5,%6,%7}, {%8,%9}, {%0,%1,%2,%3};"
                 : "+f"(c[0]), "+f"(c[1]), "+f"(c[2]), "+f"(c[3])
                 : "r"(a[0]), "r"(a[1]), "r"(a[2]), "r"(a[3]), "r"(b0), "r"(b1));
}

__device__ __forceinline__ void cp_async16(uint32_t saddr, const void* gaddr) {
    asm volatile("cp.async.cg.shared.global [%0], [%1], 16;" :: "r"(saddr), "l"(gaddr));
}
__device__ __forceinline__ void cp_commit() { asm volatile("cp.async.commit_group;"); }
__device__ __forceinline__ void cp_wait0()  { asm volatile("cp.async.wait_group 0;" ::: "memory"); }

// ============================ small kernels ============================
__global__ void k_zero() {
    int i = blockIdx.x * blockDim.x + threadIdx.x;
    if (i < N_NODES) g_cnt[i] = 0;
}

__global__ void k_count(const int* __restrict__ row) {
    int e = blockIdx.x * blockDim.x + threadIdx.x;
    if (e < E_EDGES) atomicAdd(&g_cnt[row[e]], 1);
}

__global__ __launch_bounds__(SCAN_B) void k_scan1() {
    __shared__ int wsum[SCAN_B / 32];
    int i = blockIdx.x * SCAN_B + threadIdx.x;
    int lane = threadIdx.x & 31, wid = threadIdx.x >> 5;
    int v = (i < N_NODES) ? g_cnt[i] : 0;
    if (i < N_NODES) g_cur[i] = 0;
    int s = v;
    #pragma unroll
    for (int o = 1; o < 32; o <<= 1) { int t = __shfl_up_sync(~0u, s, o); if (lane >= o) s += t; }
    if (lane == 31) wsum[wid] = s;
    __syncthreads();
    if (wid == 0) {
        int ws = (lane < SCAN_B / 32) ? wsum[lane] : 0;
        #pragma unroll
        for (int o = 1; o < SCAN_B / 32; o <<= 1) { int t = __shfl_up_sync(~0u, ws, o); if (lane >= o) ws += t; }
        if (lane < SCAN_B / 32) wsum[lane] = ws;
    }
    __syncthreads();
    int base = (wid > 0) ? wsum[wid - 1] : 0;
    if (i < N_NODES) g_off[i] = base + s - v;
    if (threadIdx.x == SCAN_B - 1) g_bsum[blockIdx.x] = base + s;
}

__global__ __launch_bounds__(256) void k_scan2() {
    __shared__ int wsum[8];
    int lane = threadIdx.x & 31, wid = threadIdx.x >> 5;
    int v = (threadIdx.x < NBLK) ? g_bsum[threadIdx.x] : 0;
    int s = v;
    #pragma unroll
    for (int o = 1; o < 32; o <<= 1) { int t = __shfl_up_sync(~0u, s, o); if (lane >= o) s += t; }
    if (lane == 31) wsum[wid] = s;
    __syncthreads();
    if (wid == 0) {
        int ws = (lane < 8) ? wsum[lane] : 0;
        #pragma unroll
        for (int o = 1; o < 8; o <<= 1) { int t = __shfl_up_sync(~0u, ws, o); if (lane >= o) ws += t; }
        if (lane < 8) wsum[lane] = ws;
    }
    __syncthreads();
    int base = (wid > 0) ? wsum[wid - 1] : 0;
    if (threadIdx.x < NBLK) g_bsum[threadIdx.x] = base + s - v;
}

__global__ __launch_bounds__(256) void k_bin(const int* __restrict__ row, const int* __restrict__ col) {
    int e = blockIdx.x * blockDim.x + threadIdx.x;
    if (e >= E_EDGES) return;
    int r = row[e];
    int pos = g_off[r] + g_bsum[r >> 9] + atomicAdd(&g_cur[r], 1);
    g_ecol[pos] = col[e];
}

// ---- pre-transpose W to fp16: g_wh[mat][n][k] ----
__global__ __launch_bounds__(256) void k_wsplit(const float* __restrict__ W_fc,
                                                const float* __restrict__ W_rate,
                                                const float* __restrict__ W_rob) {
    int t = blockIdx.x * blockDim.x + threadIdx.x;   // 3*128*32 = 12288
    if (t >= 3 * 128 * 32) return;
    int mat = t >> 12;
    int n = (t & 4095) >> 5;
    int k0 = (t & 31) << 2;
    const float* W = (mat == 0) ? W_fc : ((mat == 1) ? W_rate : W_rob);
    __half hi[4];
    #pragma unroll
    for (int i = 0; i < 4; i++)
        hi[i] = __float2half_rn(W[(size_t)(k0 + i) * D + n]);
    *(uint2*)(g_wh + ((size_t)mat << 14) + (n << 7) + k0) = *(uint2*)hi;
}

// ============================ mma.sync fused 3x GEMM ============================
// TILE_M=256, 512 threads (16 warps: 8 M-groups x 2 N-groups), 1 fp16 term.
// smem: x_hi [0,64K)  Wbuf0 [64K,96K)  Wbuf1 [96K,128K)  (double-buffered)
// fp16 [row][k] rows of 256B, 16B-unit swizzle: unit u -> u ^ (row & 7).
#define SM_XHI   0
#define SM_WB    65536
#define SM_TOTAL 131072

__global__ __launch_bounds__(MM_THREADS, 1) void k_mm(const float* __restrict__ x,
                                                      const float* __restrict__ b_fc,
                                                      const float* __restrict__ b_rob) {
    extern __shared__ char smem[];
    const uint32_t sbase = smem_u32(smem);
    const int tid = threadIdx.x;
    const int wid = tid >> 5;
    const int lane = tid & 31;
    const int m0 = blockIdx.x * TILE_M;
    const int warpM = wid & 7;     // rows 32*warpM .. +32
    const int warpN = wid >> 3;    // cols 64*warpN .. +64

    // ---- prefetch W[0] into buf0 (32KB = 2048 16B units, 4 per thread) ----
    {
        const char* wsrc = (const char*)g_wh;
        #pragma unroll
        for (int r = 0; r < 4; r++) {
            int idx = (r << 9) + tid;           // 0..2047
            int n = idx >> 4;
            int u = idx & 15;
            uint32_t dst = sbase + SM_WB + (uint32_t)(n * 256 + ((u ^ (n & 7)) << 4));
            cp_async16(dst, wsrc + (size_t)n * 256 + (u << 4));
        }
        cp_commit();
    }

    // ---- stage x tile as fp16 (256 rows x 128 k) ----
    #pragma unroll
    for (int r = 0; r < 16; r++) {
        int idx = (r << 9) + tid;           // 0..8191
        int m = idx >> 5;
        int kq = idx & 31;                  // float4 index; k0 = kq*4
        float4 v = make_float4(0.f, 0.f, 0.f, 0.f);
        if (m0 + m < N_NODES) v = *(const float4*)(x + (size_t)(m0 + m) * D + (kq << 2));
        uint2 hp;
        hp.x = __half_as_ushort(__float2half_rn(v.x)) | ((uint32_t)__half_as_ushort(__float2half_rn(v.y)) << 16);
        hp.y = __half_as_ushort(__float2half_rn(v.z)) | ((uint32_t)__half_as_ushort(__float2half_rn(v.w)) << 16);
        int u = kq >> 1;                    // 16B unit
        int off8 = (kq & 1) << 3;
        uint32_t so = (uint32_t)(m * 256 + ((u ^ (m & 7)) << 4) + off8);
        *(uint2*)(smem + SM_XHI + so) = hp;
    }
    cp_wait0();
    __syncthreads();

    // per-thread ldmatrix address components
    const int rowA_off = (lane & 7) + (((lane >> 3) & 1) << 3);
    const int dA = lane >> 4;
    const int nB_off = (lane & 7) + (((lane >> 4) & 1) << 3);
    const int dB = (lane >> 3) & 1;

    int rowA[2], s7A[2];
    #pragma unroll
    for (int mt = 0; mt < 2; mt++) {
        int rr = warpM * 32 + mt * 16 + rowA_off;
        rowA[mt] = rr * 256; s7A[mt] = rr & 7;
    }
    int rowB[4], s7B[4];
    #pragma unroll
    for (int nt2 = 0; nt2 < 4; nt2++) {
        int nn = warpN * 64 + nt2 * 16 + nB_off;
        rowB[nt2] = nn * 256; s7B[nt2] = nn & 7;
    }

    const int g4 = lane >> 2;      // C-frag row within tile
    const int t4 = lane & 3;       // C-frag col pair

    for (int mat = 0; mat < 3; mat++) {
        const int cur = mat & 1;
        float acc[2][8][4];
        #pragma unroll
        for (int mt = 0; mt < 2; mt++)
            #pragma unroll
            for (int nt = 0; nt < 8; nt++)
                #pragma unroll
                for (int i = 0; i < 4; i++) acc[mt][nt][i] = 0.f;

        const uint32_t abase = sbase + SM_XHI;
        const uint32_t bbase = sbase + SM_WB + (cur << 15);
        #pragma unroll 1
        for (int ks = 0; ks < 8; ks++) {
            uint32_t a[2][4];
            #pragma unroll
            for (int mt = 0; mt < 2; mt++) {
                int u = 2 * ks + dA;
                ldmatrix4(a[mt], abase + rowA[mt] + ((u ^ s7A[mt]) << 4));
            }
            uint32_t b[4][4];
            #pragma unroll
            for (int nt2 = 0; nt2 < 4; nt2++) {
                int u = 2 * ks + dB;
                ldmatrix4(b[nt2], bbase + rowB[nt2] + ((u ^ s7B[nt2]) << 4));
            }
            #pragma unroll
            for (int mt = 0; mt < 2; mt++)
                #pragma unroll
                for (int nt = 0; nt < 8; nt++)
                    mma16816(acc[mt][nt], a[mt], b[nt >> 1][(nt & 1) << 1], b[nt >> 1][((nt & 1) << 1) + 1]);
        }

        // prefetch next W into the OTHER buffer (safe: that buffer was last read
        // in iteration mat-1, which ended with cp_wait0+__syncthreads). Overlaps epilogue.
        if (mat < 2) {
            const char* wsrc = (const char*)g_wh + ((size_t)(mat + 1) << 15);
            #pragma unroll
            for (int r = 0; r < 4; r++) {
                int idx = (r << 9) + tid;
                int n = idx >> 4;
                int u = idx & 15;
                uint32_t dst = sbase + SM_WB + ((cur ^ 1) << 15)
                             + (uint32_t)(n * 256 + ((u ^ (n & 7)) << 4));
                cp_async16(dst, wsrc + (size_t)n * 256 + (u << 4));
            }
            cp_commit();
        }

        // ---- epilogue for this mat ----
        {
            float* outp = (mat == 0) ? g_h : ((mat == 1) ? g_rate : g_gamma);
            const float* bias = (mat == 0) ? b_fc : b_rob;
            #pragma unroll
            for (int mt = 0; mt < 2; mt++) {
                int r0 = m0 + warpM * 32 + mt * 16 + g4;
                int r1 = r0 + 8;
                #pragma unroll
                for (int nt = 0; nt < 8; nt++) {
                    int col = warpN * 64 + nt * 8 + t4 * 2;
                    float v0 = acc[mt][nt][0], v1 = acc[mt][nt][1];
                    float v2 = acc[mt][nt][2], v3 = acc[mt][nt][3];
                    if (mat == 1) {
                        v0 = ((v0 > 20.f) ? v0 : log1pf(__expf(v0))) + EPSV;
                        v1 = ((v1 > 20.f) ? v1 : log1pf(__expf(v1))) + EPSV;
                        v2 = ((v2 > 20.f) ? v2 : log1pf(__expf(v2))) + EPSV;
                        v3 = ((v3 > 20.f) ? v3 : log1pf(__expf(v3))) + EPSV;
                    } else {
                        float b0 = bias[col], b1 = bias[col + 1];
                        v0 += b0; v1 += b1; v2 += b0; v3 += b1;
                    }
                    if (r0 < N_NODES) *(float2*)(outp + (size_t)r0 * D + col) = make_float2(v0, v1);
                    if (r1 < N_NODES) *(float2*)(outp + (size_t)r1 * D + col) = make_float2(v2, v3);
                }
            }
        }

        if (mat < 2) { cp_wait0(); __syncthreads(); }
    }
}

// ---------------- fused gather + combine + LayerNorm (one warp per node) ----
__global__ __launch_bounds__(256) void k_final(const int* __restrict__ degree,
                                               const float* __restrict__ ln_g,
                                               const float* __restrict__ ln_b,
                                               float* __restrict__ out)
{
    int w = (blockIdx.x * blockDim.x + threadIdx.x) >> 5;
    int lane = threadIdx.x & 31;
    if (w >= N_NODES) return;
    size_t base = (size_t)w * D;

    int start = g_off[w] + g_bsum[w >> 9];
    int cnt = g_cnt[w];

    float4 acc = make_float4(0.f, 0.f, 0.f, 0.f);
    int j = 0;
    for (; j + 8 <= cnt; j += 8) {
        int c[8];
        #pragma unroll
        for (int q = 0; q < 8; q++) c[q] = g_ecol[start + j + q];
        float4 v[8];
        #pragma unroll
        for (int q = 0; q < 8; q++) v[q] = __ldg(((const float4*)(g_h + (size_t)c[q] * D)) + lane);
        #pragma unroll
        for (int q = 0; q < 8; q++) {
            acc.x += v[q].x; acc.y += v[q].y; acc.z += v[q].z; acc.w += v[q].w;
        }
    }
    for (; j + 4 <= cnt; j += 4) {
        int c0 = g_ecol[start + j + 0];
        int c1 = g_ecol[start + j + 1];
        int c2 = g_ecol[start + j + 2];
        int c3 = g_ecol[start + j + 3];
        float4 v0 = __ldg(((const float4*)(g_h + (size_t)c0 * D)) + lane);
        float4 v1 = __ldg(((const float4*)(g_h + (size_t)c1 * D)) + lane);
        float4 v2 = __ldg(((const float4*)(g_h + (size_t)c2 * D)) + lane);
        float4 v3 = __ldg(((const float4*)(g_h + (size_t)c3 * D)) + lane);
        acc.x += (v0.x + v1.x) + (v2.x + v3.x);
        acc.y += (v0.y + v1.y) + (v2.y + v3.y);
        acc.z += (v0.z + v1.z) + (v2.z + v3.z);
        acc.w += (v0.w + v1.w) + (v2.w + v3.w);
    }
    for (; j < cnt; j++) {
        int c = g_ecol[start + j];
        float4 v = __ldg(((const float4*)(g_h + (size_t)c * D)) + lane);
        acc.x += v.x; acc.y += v.y; acc.z += v.z; acc.w += v.w;
    }

    float4 h4 = ((const float4*)(g_h + base))[lane];
    float4 r4 = ((const float4*)(g_rate + base))[lane];
    float4 g4 = ((const float4*)(g_gamma + base))[lane];
    float fc = (float)cnt;
    float deg = (float)degree[w];

    float y[4];
    {
        const float* hp = (const float*)&h4;
        const float* ap = (const float*)&acc;
        const float* rp = (const float*)&r4;
        const float* gp = (const float*)&g4;
        #pragma unroll
        for (int i = 0; i < 4; i++) {
            float agg_full = ap[i] + fc * hp[i];
            y[i] = (rp[i] * agg_full + gp[i]) / (1.0f + EPSV + rp[i] * deg);
        }
    }

    float s = y[0] + y[1] + y[2] + y[3];
    float s2 = y[0]*y[0] + y[1]*y[1] + y[2]*y[2] + y[3]*y[3];
    #pragma unroll
    for (int off = 16; off > 0; off >>= 1) {
        s  += __shfl_xor_sync(0xffffffffu, s,  off);
        s2 += __shfl_xor_sync(0xffffffffu, s2, off);
    }
    float mean = s * (1.0f / D);
    float var = s2 * (1.0f / D) - mean * mean;
    float rstd = rsqrtf(var + LN_EPSV);

    float4 lg = ((const float4*)ln_g)[lane];
    float4 lb = ((const float4*)ln_b)[lane];
    float4 o;
    o.x = (y[0] - mean) * rstd * lg.x + lb.x;
    o.y = (y[1] - mean) * rstd * lg.y + lb.y;
    o.z = (y[2] - mean) * rstd * lg.z + lb.z;
    o.w = (y[3] - mean) * rstd * lg.w + lb.w;
    ((float4*)(out + base))[lane] = o;
}

// ---------------- launch ----------------
extern "C" void kernel_launch(void* const* d_in, const int* in_sizes, int n_in,
                              void* d_out, int out_size) {
    const float* x      = (const float*)d_in[0];
    const int*   ei     = (const int*)  d_in[1];
    const int*   degree = (const int*)  d_in[2];
    const float* W_fc   = (const float*)d_in[3];
    const float* b_fc   = (const float*)d_in[4];
    const float* W_rate = (const float*)d_in[5];
    const float* W_rob  = (const float*)d_in[6];
    const float* b_rob  = (const float*)d_in[7];
    const float* ln_g   = (const float*)d_in[8];
    const float* ln_b   = (const float*)d_in[9];
    float* out = (float*)d_out;

    const int* row = ei;             // edge_index[0]
    const int* col = ei + E_EDGES;   // edge_index[1]

    // one-time setup (outside capture on the first/correctness call)
    static cudaStream_t sideStream = nullptr;
    static cudaEvent_t evRoot = nullptr, evSide = nullptr;
    if (!sideStream) {
        cudaStreamCreateWithFlags(&sideStream, cudaStreamNonBlocking);
        cudaEventCreateWithFlags(&evRoot, cudaEventDisableTiming);
        cudaEventCreateWithFlags(&evSide, cudaEventDisableTiming);
        cudaFuncSetAttribute(k_mm, cudaFuncAttributeMaxDynamicSharedMemorySize, SM_TOTAL);
    }

    // fork: CSR build on side stream, GEMM on main stream
    cudaEventRecord(evRoot, 0);
    cudaStreamWaitEvent(sideStream, evRoot, 0);

    // side stream: CSR build chain (latency-bound small kernels — hides under GEMM)
    k_zero<<<(N_NODES + 255) / 256, 256, 0, sideStream>>>();
    k_count<<<(E_EDGES + 255) / 256, 256, 0, sideStream>>>(row);
    k_scan1<<<NBLK, SCAN_B, 0, sideStream>>>();
    k_scan2<<<1, 256, 0, sideStream>>>();
    k_bin<<<(E_EDGES + 255) / 256, 256, 0, sideStream>>>(row, col);
    cudaEventRecord(evSide, sideStream);

    // main stream: weight convert + tensor-core GEMM
    k_wsplit<<<(3 * 128 * 32 + 255) / 256, 256>>>(W_fc, W_rate, W_rob);
    k_mm<<<MM_CTAS, MM_THREADS, SM_TOTAL>>>(x, b_fc, b_rob);

    // join, then fused gather + LayerNorm
    cudaStreamWaitEvent(0, evSide, 0);
    k_final<<<(int)(((size_t)N_NODES * 32 + 255) / 256), 256>>>(degree, ln_g, ln_b, out);
}

// round 15
// speedup vs baseline: 1.4028x; 1.1398x over previous
#include <cuda_runtime.h>
#include <cuda_fp16.h>
#include <math.h>
#include <cstdint>

#define N_NODES 100000
#define E_EDGES 800000
#define D 128
#define EPSV 1e-4f
#define LN_EPSV 1e-5f

#define SCAN_B 512
#define NBLK ((N_NODES + SCAN_B - 1) / SCAN_B)   // 196

#define TILE_M 256
#define MM_CTAS ((N_NODES + TILE_M - 1) / TILE_M)  // 391
#define MM_THREADS 512

// ---- scratch (device globals; no allocation allowed) ----
__device__ __half g_hh[(size_t)N_NODES * D];     // h in fp16 (gather payload)
__device__ float  g_rate[(size_t)N_NODES * D];
__device__ float  g_gamma[(size_t)N_NODES * D];
__device__ int    g_cnt[N_NODES];
__device__ int    g_cur[N_NODES];
__device__ int    g_off[N_NODES];
__device__ int    g_bsum[NBLK];
__device__ int    g_ecol[E_EDGES];
// fp16 transposed weights: [mat(3)][n(128)][k(128)] halves (32KB per mat)
__device__ __half g_wh[3 * 128 * 128];

// ============================ helpers ============================
__device__ __forceinline__ uint32_t smem_u32(const void* p) {
    uint32_t a;
    asm("{ .reg .u64 t; cvta.to.shared.u64 t, %1; cvt.u32.u64 %0, t; }" : "=r"(a) : "l"(p));
    return a;
}

__device__ __forceinline__ void ldmatrix4(uint32_t* r, uint32_t addr) {
    asm volatile("ldmatrix.sync.aligned.m8n8.x4.shared.b16 {%0,%1,%2,%3}, [%4];"
                 : "=r"(r[0]), "=r"(r[1]), "=r"(r[2]), "=r"(r[3]) : "r"(addr));
}

__device__ __forceinline__ void mma16816(float* c, const uint32_t* a, uint32_t b0, uint32_t b1) {
    asm volatile("mma.sync.aligned.m16n8k16.row.col.f32.f16.f16.f32 "
                 "{%0,%1,%2,%3}, {%4,%5,%6,%7}, {%8,%9}, {%0,%1,%2,%3};"
                 : "+f"(c[0]), "+f"(c[1]), "+f"(c[2]), "+f"(c[3])
                 : "r"(a[0]), "r"(a[1]), "r"(a[2]), "r"(a[3]), "r"(b0), "r"(b1));
}

__device__ __forceinline__ void cp_async16(uint32_t saddr, const void* gaddr) {
    asm volatile("cp.async.cg.shared.global [%0], [%1], 16;" :: "r"(saddr), "l"(gaddr));
}
__device__ __forceinline__ void cp_commit() { asm volatile("cp.async.commit_group;"); }
__device__ __forceinline__ void cp_wait0()  { asm volatile("cp.async.wait_group 0;" ::: "memory"); }

// ============================ small kernels ============================
__global__ void k_zero() {
    int i = blockIdx.x * blockDim.x + threadIdx.x;
    if (i < N_NODES) g_cnt[i] = 0;
}

__global__ void k_count(const int* __restrict__ row) {
    int e = blockIdx.x * blockDim.x + threadIdx.x;
    if (e < E_EDGES) atomicAdd(&g_cnt[row[e]], 1);
}

__global__ __launch_bounds__(SCAN_B) void k_scan1() {
    __shared__ int wsum[SCAN_B / 32];
    int i = blockIdx.x * SCAN_B + threadIdx.x;
    int lane = threadIdx.x & 31, wid = threadIdx.x >> 5;
    int v = (i < N_NODES) ? g_cnt[i] : 0;
    if (i < N_NODES) g_cur[i] = 0;
    int s = v;
    #pragma unroll
    for (int o = 1; o < 32; o <<= 1) { int t = __shfl_up_sync(~0u, s, o); if (lane >= o) s += t; }
    if (lane == 31) wsum[wid] = s;
    __syncthreads();
    if (wid == 0) {
        int ws = (lane < SCAN_B / 32) ? wsum[lane] : 0;
        #pragma unroll
        for (int o = 1; o < SCAN_B / 32; o <<= 1) { int t = __shfl_up_sync(~0u, ws, o); if (lane >= o) ws += t; }
        if (lane < SCAN_B / 32) wsum[lane] = ws;
    }
    __syncthreads();
    int base = (wid > 0) ? wsum[wid - 1] : 0;
    if (i < N_NODES) g_off[i] = base + s - v;
    if (threadIdx.x == SCAN_B - 1) g_bsum[blockIdx.x] = base + s;
}

__global__ __launch_bounds__(256) void k_scan2() {
    __shared__ int wsum[8];
    int lane = threadIdx.x & 31, wid = threadIdx.x >> 5;
    int v = (threadIdx.x < NBLK) ? g_bsum[threadIdx.x] : 0;
    int s = v;
    #pragma unroll
    for (int o = 1; o < 32; o <<= 1) { int t = __shfl_up_sync(~0u, s, o); if (lane >= o) s += t; }
    if (lane == 31) wsum[wid] = s;
    __syncthreads();
    if (wid == 0) {
        int ws = (lane < 8) ? wsum[lane] : 0;
        #pragma unroll
        for (int o = 1; o < 8; o <<= 1) { int t = __shfl_up_sync(~0u, ws, o); if (lane >= o) ws += t; }
        if (lane < 8) wsum[lane] = ws;
    }
    __syncthreads();
    int base = (wid > 0) ? wsum[wid - 1] : 0;
    if (threadIdx.x < NBLK) g_bsum[threadIdx.x] = base + s - v;
}

__global__ __launch_bounds__(256) void k_bin(const int* __restrict__ row, const int* __restrict__ col) {
    int e = blockIdx.x * blockDim.x + threadIdx.x;
    if (e >= E_EDGES) return;
    int r = row[e];
    int pos = g_off[r] + g_bsum[r >> 9] + atomicAdd(&g_cur[r], 1);
    g_ecol[pos] = col[e];
}

// ---- pre-transpose W to fp16: g_wh[mat][n][k] ----
__global__ __launch_bounds__(256) void k_wsplit(const float* __restrict__ W_fc,
                                                const float* __restrict__ W_rate,
                                                const float* __restrict__ W_rob) {
    int t = blockIdx.x * blockDim.x + threadIdx.x;   // 3*128*32 = 12288
    if (t >= 3 * 128 * 32) return;
    int mat = t >> 12;
    int n = (t & 4095) >> 5;
    int k0 = (t & 31) << 2;
    const float* W = (mat == 0) ? W_fc : ((mat == 1) ? W_rate : W_rob);
    __half hi[4];
    #pragma unroll
    for (int i = 0; i < 4; i++)
        hi[i] = __float2half_rn(W[(size_t)(k0 + i) * D + n]);
    *(uint2*)(g_wh + ((size_t)mat << 14) + (n << 7) + k0) = *(uint2*)hi;
}

// ============================ mma.sync fused 3x GEMM ============================
// TILE_M=256, 512 threads (16 warps: 8 M-groups x 2 N-groups), 1 fp16 term.
// smem: x_hi [0,64K)  Wbuf0 [64K,96K)  Wbuf1 [96K,128K)  (double-buffered)
// fp16 [row][k] rows of 256B, 16B-unit swizzle: unit u -> u ^ (row & 7).
#define SM_XHI   0
#define SM_WB    65536
#define SM_TOTAL 131072

__global__ __launch_bounds__(MM_THREADS, 1) void k_mm(const float* __restrict__ x,
                                                      const float* __restrict__ b_fc,
                                                      const float* __restrict__ b_rob) {
    extern __shared__ char smem[];
    const uint32_t sbase = smem_u32(smem);
    const int tid = threadIdx.x;
    const int wid = tid >> 5;
    const int lane = tid & 31;
    const int m0 = blockIdx.x * TILE_M;
    const int warpM = wid & 7;     // rows 32*warpM .. +32
    const int warpN = wid >> 3;    // cols 64*warpN .. +64

    // ---- prefetch W[0] into buf0 (32KB = 2048 16B units, 4 per thread) ----
    {
        const char* wsrc = (const char*)g_wh;
        #pragma unroll
        for (int r = 0; r < 4; r++) {
            int idx = (r << 9) + tid;           // 0..2047
            int n = idx >> 4;
            int u = idx & 15;
            uint32_t dst = sbase + SM_WB + (uint32_t)(n * 256 + ((u ^ (n & 7)) << 4));
            cp_async16(dst, wsrc + (size_t)n * 256 + (u << 4));
        }
        cp_commit();
    }

    // ---- stage x tile as fp16 (256 rows x 128 k) ----
    #pragma unroll
    for (int r = 0; r < 16; r++) {
        int idx = (r << 9) + tid;           // 0..8191
        int m = idx >> 5;
        int kq = idx & 31;                  // float4 index; k0 = kq*4
        float4 v = make_float4(0.f, 0.f, 0.f, 0.f);
        if (m0 + m < N_NODES) v = *(const float4*)(x + (size_t)(m0 + m) * D + (kq << 2));
        uint2 hp;
        hp.x = __half_as_ushort(__float2half_rn(v.x)) | ((uint32_t)__half_as_ushort(__float2half_rn(v.y)) << 16);
        hp.y = __half_as_ushort(__float2half_rn(v.z)) | ((uint32_t)__half_as_ushort(__float2half_rn(v.w)) << 16);
        int u = kq >> 1;                    // 16B unit
        int off8 = (kq & 1) << 3;
        uint32_t so = (uint32_t)(m * 256 + ((u ^ (m & 7)) << 4) + off8);
        *(uint2*)(smem + SM_XHI + so) = hp;
    }
    cp_wait0();
    __syncthreads();

    // per-thread ldmatrix address components
    const int rowA_off = (lane & 7) + (((lane >> 3) & 1) << 3);
    const int dA = lane >> 4;
    const int nB_off = (lane & 7) + (((lane >> 4) & 1) << 3);
    const int dB = (lane >> 3) & 1;

    int rowA[2], s7A[2];
    #pragma unroll
    for (int mt = 0; mt < 2; mt++) {
        int rr = warpM * 32 + mt * 16 + rowA_off;
        rowA[mt] = rr * 256; s7A[mt] = rr & 7;
    }
    int rowB[4], s7B[4];
    #pragma unroll
    for (int nt2 = 0; nt2 < 4; nt2++) {
        int nn = warpN * 64 + nt2 * 16 + nB_off;
        rowB[nt2] = nn * 256; s7B[nt2] = nn & 7;
    }

    const int g4 = lane >> 2;      // C-frag row within tile
    const int t4 = lane & 3;       // C-frag col pair

    for (int mat = 0; mat < 3; mat++) {
        const int cur = mat & 1;
        float acc[2][8][4];
        #pragma unroll
        for (int mt = 0; mt < 2; mt++)
            #pragma unroll
            for (int nt = 0; nt < 8; nt++)
                #pragma unroll
                for (int i = 0; i < 4; i++) acc[mt][nt][i] = 0.f;

        const uint32_t abase = sbase + SM_XHI;
        const uint32_t bbase = sbase + SM_WB + (cur << 15);
        #pragma unroll 1
        for (int ks = 0; ks < 8; ks++) {
            uint32_t a[2][4];
            #pragma unroll
            for (int mt = 0; mt < 2; mt++) {
                int u = 2 * ks + dA;
                ldmatrix4(a[mt], abase + rowA[mt] + ((u ^ s7A[mt]) << 4));
            }
            uint32_t b[4][4];
            #pragma unroll
            for (int nt2 = 0; nt2 < 4; nt2++) {
                int u = 2 * ks + dB;
                ldmatrix4(b[nt2], bbase + rowB[nt2] + ((u ^ s7B[nt2]) << 4));
            }
            #pragma unroll
            for (int mt = 0; mt < 2; mt++)
                #pragma unroll
                for (int nt = 0; nt < 8; nt++)
                    mma16816(acc[mt][nt], a[mt], b[nt >> 1][(nt & 1) << 1], b[nt >> 1][((nt & 1) << 1) + 1]);
        }

        // prefetch next W into the OTHER buffer (safe: last read in mat-1,
        // fenced by that iteration's cp_wait0+__syncthreads). Overlaps epilogue.
        if (mat < 2) {
            const char* wsrc = (const char*)g_wh + ((size_t)(mat + 1) << 15);
            #pragma unroll
            for (int r = 0; r < 4; r++) {
                int idx = (r << 9) + tid;
                int n = idx >> 4;
                int u = idx & 15;
                uint32_t dst = sbase + SM_WB + ((cur ^ 1) << 15)
                             + (uint32_t)(n * 256 + ((u ^ (n & 7)) << 4));
                cp_async16(dst, wsrc + (size_t)n * 256 + (u << 4));
            }
            cp_commit();
        }

        // ---- epilogue for this mat ----
        if (mat == 0) {
            // h -> fp16 g_hh only (halves gather traffic downstream)
            #pragma unroll
            for (int mt = 0; mt < 2; mt++) {
                int r0 = m0 + warpM * 32 + mt * 16 + g4;
                int r1 = r0 + 8;
                #pragma unroll
                for (int nt = 0; nt < 8; nt++) {
                    int col = warpN * 64 + nt * 8 + t4 * 2;
                    float b0 = b_fc[col], b1 = b_fc[col + 1];
                    __half2 ha = __floats2half2_rn(acc[mt][nt][0] + b0, acc[mt][nt][1] + b1);
                    __half2 hb = __floats2half2_rn(acc[mt][nt][2] + b0, acc[mt][nt][3] + b1);
                    if (r0 < N_NODES) *(__half2*)(g_hh + (size_t)r0 * D + col) = ha;
                    if (r1 < N_NODES) *(__half2*)(g_hh + (size_t)r1 * D + col) = hb;
                }
            }
        } else {
            float* outp = (mat == 1) ? g_rate : g_gamma;
            #pragma unroll
            for (int mt = 0; mt < 2; mt++) {
                int r0 = m0 + warpM * 32 + mt * 16 + g4;
                int r1 = r0 + 8;
                #pragma unroll
                for (int nt = 0; nt < 8; nt++) {
                    int col = warpN * 64 + nt * 8 + t4 * 2;
                    float v0 = acc[mt][nt][0], v1 = acc[mt][nt][1];
                    float v2 = acc[mt][nt][2], v3 = acc[mt][nt][3];
                    if (mat == 1) {
                        v0 = ((v0 > 20.f) ? v0 : log1pf(__expf(v0))) + EPSV;
                        v1 = ((v1 > 20.f) ? v1 : log1pf(__expf(v1))) + EPSV;
                        v2 = ((v2 > 20.f) ? v2 : log1pf(__expf(v2))) + EPSV;
                        v3 = ((v3 > 20.f) ? v3 : log1pf(__expf(v3))) + EPSV;
                    } else {
                        float b0 = b_rob[col], b1 = b_rob[col + 1];
                        v0 += b0; v1 += b1; v2 += b0; v3 += b1;
                    }
                    if (r0 < N_NODES) *(float2*)(outp + (size_t)r0 * D + col) = make_float2(v0, v1);
                    if (r1 < N_NODES) *(float2*)(outp + (size_t)r1 * D + col) = make_float2(v2, v3);
                }
            }
        }

        if (mat < 2) { cp_wait0(); __syncthreads(); }
    }
}

// ---------------- fused gather(fp16) + combine + LayerNorm (one warp per node) ----
__global__ __launch_bounds__(256) void k_final(const int* __restrict__ degree,
                                               const float* __restrict__ ln_g,
                                               const float* __restrict__ ln_b,
                                               float* __restrict__ out)
{
    int w = (blockIdx.x * blockDim.x + threadIdx.x) >> 5;
    int lane = threadIdx.x & 31;
    if (w >= N_NODES) return;
    size_t base = (size_t)w * D;

    int start = g_off[w] + g_bsum[w >> 9];
    int cnt = g_cnt[w];

    // each lane handles 4 consecutive h-cols: bytes [lane*8, lane*8+8) of each 256B row
    float4 acc = make_float4(0.f, 0.f, 0.f, 0.f);
    int j = 0;
    for (; j + 8 <= cnt; j += 8) {
        int c[8];
        #pragma unroll
        for (int q = 0; q < 8; q++) c[q] = g_ecol[start + j + q];
        uint2 p[8];
        #pragma unroll
        for (int q = 0; q < 8; q++) p[q] = __ldg(((const uint2*)(g_hh + (size_t)c[q] * D)) + lane);
        #pragma unroll
        for (int q = 0; q < 8; q++) {
            float2 f01 = __half22float2(*(__half2*)&p[q].x);
            float2 f23 = __half22float2(*(__half2*)&p[q].y);
            acc.x += f01.x; acc.y += f01.y; acc.z += f23.x; acc.w += f23.y;
        }
    }
    for (; j < cnt; j++) {
        int c = g_ecol[start + j];
        uint2 p = __ldg(((const uint2*)(g_hh + (size_t)c * D)) + lane);
        float2 f01 = __half22float2(*(__half2*)&p.x);
        float2 f23 = __half22float2(*(__half2*)&p.y);
        acc.x += f01.x; acc.y += f01.y; acc.z += f23.x; acc.w += f23.y;
    }

    // self h (fp16), rate/gamma fp32 — all at cols lane*4..lane*4+3
    uint2 ph = ((const uint2*)(g_hh + base))[lane];
    float2 h01 = __half22float2(*(__half2*)&ph.x);
    float2 h23 = __half22float2(*(__half2*)&ph.y);
    float hv[4] = {h01.x, h01.y, h23.x, h23.y};
    float4 r4 = ((const float4*)(g_rate + base))[lane];
    float4 g4 = ((const float4*)(g_gamma + base))[lane];
    float fc = (float)cnt;
    float deg = (float)degree[w];

    float y[4];
    {
        const float* ap = (const float*)&acc;
        const float* rp = (const float*)&r4;
        const float* gp = (const float*)&g4;
        #pragma unroll
        for (int i = 0; i < 4; i++) {
            float agg_full = ap[i] + fc * hv[i];
            y[i] = (rp[i] * agg_full + gp[i]) / (1.0f + EPSV + rp[i] * deg);
        }
    }

    float s = y[0] + y[1] + y[2] + y[3];
    float s2 = y[0]*y[0] + y[1]*y[1] + y[2]*y[2] + y[3]*y[3];
    #pragma unroll
    for (int off = 16; off > 0; off >>= 1) {
        s  += __shfl_xor_sync(0xffffffffu, s,  off);
        s2 += __shfl_xor_sync(0xffffffffu, s2, off);
    }
    float mean = s * (1.0f / D);
    float var = s2 * (1.0f / D) - mean * mean;
    float rstd = rsqrtf(var + LN_EPSV);

    float4 lg = ((const float4*)ln_g)[lane];
    float4 lb = ((const float4*)ln_b)[lane];
    float4 o;
    o.x = (y[0] - mean) * rstd * lg.x + lb.x;
    o.y = (y[1] - mean) * rstd * lg.y + lb.y;
    o.z = (y[2] - mean) * rstd * lg.z + lb.z;
    o.w = (y[3] - mean) * rstd * lg.w + lb.w;
    ((float4*)(out + base))[lane] = o;
}

// ---------------- launch ----------------
extern "C" void kernel_launch(void* const* d_in, const int* in_sizes, int n_in,
                              void* d_out, int out_size) {
    const float* x      = (const float*)d_in[0];
    const int*   ei     = (const int*)  d_in[1];
    const int*   degree = (const int*)  d_in[2];
    const float* W_fc   = (const float*)d_in[3];
    const float* b_fc   = (const float*)d_in[4];
    const float* W_rate = (const float*)d_in[5];
    const float* W_rob  = (const float*)d_in[6];
    const float* b_rob  = (const float*)d_in[7];
    const float* ln_g   = (const float*)d_in[8];
    const float* ln_b   = (const float*)d_in[9];
    float* out = (float*)d_out;

    const int* row = ei;             // edge_index[0]
    const int* col = ei + E_EDGES;   // edge_index[1]

    // one-time setup (outside capture on the first/correctness call)
    static cudaStream_t sideStream = nullptr;
    static cudaEvent_t evRoot = nullptr, evSide = nullptr;
    if (!sideStream) {
        cudaStreamCreateWithFlags(&sideStream, cudaStreamNonBlocking);
        cudaEventCreateWithFlags(&evRoot, cudaEventDisableTiming);
        cudaEventCreateWithFlags(&evSide, cudaEventDisableTiming);
        cudaFuncSetAttribute(k_mm, cudaFuncAttributeMaxDynamicSharedMemorySize, SM_TOTAL);
    }

    // fork: CSR build on side stream, GEMM on main stream
    cudaEventRecord(evRoot, 0);
    cudaStreamWaitEvent(sideStream, evRoot, 0);

    // side stream: CSR build chain (latency-bound small kernels — hides under GEMM)
    k_zero<<<(N_NODES + 255) / 256, 256, 0, sideStream>>>();
    k_count<<<(E_EDGES + 255) / 256, 256, 0, sideStream>>>(row);
    k_scan1<<<NBLK, SCAN_B, 0, sideStream>>>();
    k_scan2<<<1, 256, 0, sideStream>>>();
    k_bin<<<(E_EDGES + 255) / 256, 256, 0, sideStream>>>(row, col);
    cudaEventRecord(evSide, sideStream);

    // main stream: weight convert + tensor-core GEMM
    k_wsplit<<<(3 * 128 * 32 + 255) / 256, 256>>>(W_fc, W_rate, W_rob);
    k_mm<<<MM_CTAS, MM_THREADS, SM_TOTAL>>>(x, b_fc, b_rob);

    // join, then fused gather + LayerNorm
    cudaStreamWaitEvent(0, evSide, 0);
    k_final<<<(int)(((size_t)N_NODES * 32 + 255) / 256), 256>>>(degree, ln_g, ln_b, out);
}

// round 16
// speedup vs baseline: 1.4561x; 1.0380x over previous
#include <cuda_runtime.h>
#include <cuda_fp16.h>
#include <math.h>
#include <cstdint>

#define N_NODES 100000
#define E_EDGES 800000
#define D 128
#define EPSV 1e-4f
#define LN_EPSV 1e-5f

#define SCAN_B 512
#define NBLK ((N_NODES + SCAN_B - 1) / SCAN_B)   // 196

#define TILE_M 256
#define MM_CTAS ((N_NODES + TILE_M - 1) / TILE_M)  // 391
#define MM_THREADS 512

// ---- scratch (device globals; no allocation allowed) ----
__device__ __half g_hh[(size_t)N_NODES * D];      // h in fp16
__device__ __half g_rateh[(size_t)N_NODES * D];   // softplus(x@W_rate)+eps in fp16
__device__ __half g_gammah[(size_t)N_NODES * D];  // x@W_rob + b_rob in fp16
__device__ int    g_cnt[N_NODES];
__device__ int    g_cur[N_NODES];
__device__ int    g_off[N_NODES];
__device__ int    g_bsum[NBLK];
__device__ int    g_ecol[E_EDGES];
// fp16 transposed weights: [mat(3)][n(128)][k(128)] halves (32KB per mat)
__device__ __half g_wh[3 * 128 * 128];

// ============================ helpers ============================
__device__ __forceinline__ uint32_t smem_u32(const void* p) {
    uint32_t a;
    asm("{ .reg .u64 t; cvta.to.shared.u64 t, %1; cvt.u32.u64 %0, t; }" : "=r"(a) : "l"(p));
    return a;
}

__device__ __forceinline__ void ldmatrix4(uint32_t* r, uint32_t addr) {
    asm volatile("ldmatrix.sync.aligned.m8n8.x4.shared.b16 {%0,%1,%2,%3}, [%4];"
                 : "=r"(r[0]), "=r"(r[1]), "=r"(r[2]), "=r"(r[3]) : "r"(addr));
}

__device__ __forceinline__ void mma16816(float* c, const uint32_t* a, uint32_t b0, uint32_t b1) {
    asm volatile("mma.sync.aligned.m16n8k16.row.col.f32.f16.f16.f32 "
                 "{%0,%1,%2,%3}, {%4,%5,%6,%7}, {%8,%9}, {%0,%1,%2,%3};"
                 : "+f"(c[0]), "+f"(c[1]), "+f"(c[2]), "+f"(c[3])
                 : "r"(a[0]), "r"(a[1]), "r"(a[2]), "r"(a[3]), "r"(b0), "r"(b1));
}

__device__ __forceinline__ void cp_async16(uint32_t saddr, const void* gaddr) {
    asm volatile("cp.async.cg.shared.global [%0], [%1], 16;" :: "r"(saddr), "l"(gaddr));
}
__device__ __forceinline__ void cp_commit() { asm volatile("cp.async.commit_group;"); }
__device__ __forceinline__ void cp_wait0()  { asm volatile("cp.async.wait_group 0;" ::: "memory"); }

// ============================ small kernels ============================
__global__ void k_zero() {
    int i = blockIdx.x * blockDim.x + threadIdx.x;
    if (i < N_NODES) g_cnt[i] = 0;
}

__global__ void k_count(const int* __restrict__ row) {
    int e = blockIdx.x * blockDim.x + threadIdx.x;
    if (e < E_EDGES) atomicAdd(&g_cnt[row[e]], 1);
}

__global__ __launch_bounds__(SCAN_B) void k_scan1() {
    __shared__ int wsum[SCAN_B / 32];
    int i = blockIdx.x * SCAN_B + threadIdx.x;
    int lane = threadIdx.x & 31, wid = threadIdx.x >> 5;
    int v = (i < N_NODES) ? g_cnt[i] : 0;
    if (i < N_NODES) g_cur[i] = 0;
    int s = v;
    #pragma unroll
    for (int o = 1; o < 32; o <<= 1) { int t = __shfl_up_sync(~0u, s, o); if (lane >= o) s += t; }
    if (lane == 31) wsum[wid] = s;
    __syncthreads();
    if (wid == 0) {
        int ws = (lane < SCAN_B / 32) ? wsum[lane] : 0;
        #pragma unroll
        for (int o = 1; o < SCAN_B / 32; o <<= 1) { int t = __shfl_up_sync(~0u, ws, o); if (lane >= o) ws += t; }
        if (lane < SCAN_B / 32) wsum[lane] = ws;
    }
    __syncthreads();
    int base = (wid > 0) ? wsum[wid - 1] : 0;
    if (i < N_NODES) g_off[i] = base + s - v;
    if (threadIdx.x == SCAN_B - 1) g_bsum[blockIdx.x] = base + s;
}

__global__ __launch_bounds__(256) void k_scan2() {
    __shared__ int wsum[8];
    int lane = threadIdx.x & 31, wid = threadIdx.x >> 5;
    int v = (threadIdx.x < NBLK) ? g_bsum[threadIdx.x] : 0;
    int s = v;
    #pragma unroll
    for (int o = 1; o < 32; o <<= 1) { int t = __shfl_up_sync(~0u, s, o); if (lane >= o) s += t; }
    if (lane == 31) wsum[wid] = s;
    __syncthreads();
    if (wid == 0) {
        int ws = (lane < 8) ? wsum[lane] : 0;
        #pragma unroll
        for (int o = 1; o < 8; o <<= 1) { int t = __shfl_up_sync(~0u, ws, o); if (lane >= o) ws += t; }
        if (lane < 8) wsum[lane] = ws;
    }
    __syncthreads();
    int base = (wid > 0) ? wsum[wid - 1] : 0;
    if (threadIdx.x < NBLK) g_bsum[threadIdx.x] = base + s - v;
}

__global__ __launch_bounds__(256) void k_bin(const int* __restrict__ row, const int* __restrict__ col) {
    int e = blockIdx.x * blockDim.x + threadIdx.x;
    if (e >= E_EDGES) return;
    int r = row[e];
    int pos = g_off[r] + g_bsum[r >> 9] + atomicAdd(&g_cur[r], 1);
    g_ecol[pos] = col[e];
}

// ---- pre-transpose W to fp16: g_wh[mat][n][k] ----
__global__ __launch_bounds__(256) void k_wsplit(const float* __restrict__ W_fc,
                                                const float* __restrict__ W_rate,
                                                const float* __restrict__ W_rob) {
    int t = blockIdx.x * blockDim.x + threadIdx.x;   // 3*128*32 = 12288
    if (t >= 3 * 128 * 32) return;
    int mat = t >> 12;
    int n = (t & 4095) >> 5;
    int k0 = (t & 31) << 2;
    const float* W = (mat == 0) ? W_fc : ((mat == 1) ? W_rate : W_rob);
    __half hi[4];
    #pragma unroll
    for (int i = 0; i < 4; i++)
        hi[i] = __float2half_rn(W[(size_t)(k0 + i) * D + n]);
    *(uint2*)(g_wh + ((size_t)mat << 14) + (n << 7) + k0) = *(uint2*)hi;
}

// ============================ mma.sync fused 3x GEMM ============================
// TILE_M=256, 512 threads (16 warps: 8 M-groups x 2 N-groups), 1 fp16 term.
// smem: x_hi [0,64K)  Wbuf0 [64K,96K)  Wbuf1 [96K,128K)  (double-buffered)
// fp16 [row][k] rows of 256B, 16B-unit swizzle: unit u -> u ^ (row & 7).
#define SM_XHI   0
#define SM_WB    65536
#define SM_TOTAL 131072

__global__ __launch_bounds__(MM_THREADS, 1) void k_mm(const float* __restrict__ x,
                                                      const float* __restrict__ b_fc,
                                                      const float* __restrict__ b_rob) {
    extern __shared__ char smem[];
    const uint32_t sbase = smem_u32(smem);
    const int tid = threadIdx.x;
    const int wid = tid >> 5;
    const int lane = tid & 31;
    const int m0 = blockIdx.x * TILE_M;
    const int warpM = wid & 7;     // rows 32*warpM .. +32
    const int warpN = wid >> 3;    // cols 64*warpN .. +64

    // ---- prefetch W[0] into buf0 (32KB = 2048 16B units, 4 per thread) ----
    {
        const char* wsrc = (const char*)g_wh;
        #pragma unroll
        for (int r = 0; r < 4; r++) {
            int idx = (r << 9) + tid;           // 0..2047
            int n = idx >> 4;
            int u = idx & 15;
            uint32_t dst = sbase + SM_WB + (uint32_t)(n * 256 + ((u ^ (n & 7)) << 4));
            cp_async16(dst, wsrc + (size_t)n * 256 + (u << 4));
        }
        cp_commit();
    }

    // ---- stage x tile as fp16 (256 rows x 128 k) ----
    #pragma unroll
    for (int r = 0; r < 16; r++) {
        int idx = (r << 9) + tid;           // 0..8191
        int m = idx >> 5;
        int kq = idx & 31;                  // float4 index; k0 = kq*4
        float4 v = make_float4(0.f, 0.f, 0.f, 0.f);
        if (m0 + m < N_NODES) v = *(const float4*)(x + (size_t)(m0 + m) * D + (kq << 2));
        uint2 hp;
        hp.x = __half_as_ushort(__float2half_rn(v.x)) | ((uint32_t)__half_as_ushort(__float2half_rn(v.y)) << 16);
        hp.y = __half_as_ushort(__float2half_rn(v.z)) | ((uint32_t)__half_as_ushort(__float2half_rn(v.w)) << 16);
        int u = kq >> 1;                    // 16B unit
        int off8 = (kq & 1) << 3;
        uint32_t so = (uint32_t)(m * 256 + ((u ^ (m & 7)) << 4) + off8);
        *(uint2*)(smem + SM_XHI + so) = hp;
    }
    cp_wait0();
    __syncthreads();

    // per-thread ldmatrix address components
    const int rowA_off = (lane & 7) + (((lane >> 3) & 1) << 3);
    const int dA = lane >> 4;
    const int nB_off = (lane & 7) + (((lane >> 4) & 1) << 3);
    const int dB = (lane >> 3) & 1;

    int rowA[2], s7A[2];
    #pragma unroll
    for (int mt = 0; mt < 2; mt++) {
        int rr = warpM * 32 + mt * 16 + rowA_off;
        rowA[mt] = rr * 256; s7A[mt] = rr & 7;
    }
    int rowB[4], s7B[4];
    #pragma unroll
    for (int nt2 = 0; nt2 < 4; nt2++) {
        int nn = warpN * 64 + nt2 * 16 + nB_off;
        rowB[nt2] = nn * 256; s7B[nt2] = nn & 7;
    }

    const int g4 = lane >> 2;      // C-frag row within tile
    const int t4 = lane & 3;       // C-frag col pair

    for (int mat = 0; mat < 3; mat++) {
        const int cur = mat & 1;
        float acc[2][8][4];
        #pragma unroll
        for (int mt = 0; mt < 2; mt++)
            #pragma unroll
            for (int nt = 0; nt < 8; nt++)
                #pragma unroll
                for (int i = 0; i < 4; i++) acc[mt][nt][i] = 0.f;

        const uint32_t abase = sbase + SM_XHI;
        const uint32_t bbase = sbase + SM_WB + (cur << 15);
        #pragma unroll 1
        for (int ks = 0; ks < 8; ks++) {
            uint32_t a[2][4];
            #pragma unroll
            for (int mt = 0; mt < 2; mt++) {
                int u = 2 * ks + dA;
                ldmatrix4(a[mt], abase + rowA[mt] + ((u ^ s7A[mt]) << 4));
            }
            uint32_t b[4][4];
            #pragma unroll
            for (int nt2 = 0; nt2 < 4; nt2++) {
                int u = 2 * ks + dB;
                ldmatrix4(b[nt2], bbase + rowB[nt2] + ((u ^ s7B[nt2]) << 4));
            }
            #pragma unroll
            for (int mt = 0; mt < 2; mt++)
                #pragma unroll
                for (int nt = 0; nt < 8; nt++)
                    mma16816(acc[mt][nt], a[mt], b[nt >> 1][(nt & 1) << 1], b[nt >> 1][((nt & 1) << 1) + 1]);
        }

        // prefetch next W into the OTHER buffer (safe: last read in mat-1,
        // fenced by that iteration's cp_wait0+__syncthreads). Overlaps epilogue.
        if (mat < 2) {
            const char* wsrc = (const char*)g_wh + ((size_t)(mat + 1) << 15);
            #pragma unroll
            for (int r = 0; r < 4; r++) {
                int idx = (r << 9) + tid;
                int n = idx >> 4;
                int u = idx & 15;
                uint32_t dst = sbase + SM_WB + ((cur ^ 1) << 15)
                             + (uint32_t)(n * 256 + ((u ^ (n & 7)) << 4));
                cp_async16(dst, wsrc + (size_t)n * 256 + (u << 4));
            }
            cp_commit();
        }

        // ---- epilogue for this mat: all outputs fp16 ----
        {
            __half* outp = (mat == 0) ? g_hh : ((mat == 1) ? g_rateh : g_gammah);
            #pragma unroll
            for (int mt = 0; mt < 2; mt++) {
                int r0 = m0 + warpM * 32 + mt * 16 + g4;
                int r1 = r0 + 8;
                #pragma unroll
                for (int nt = 0; nt < 8; nt++) {
                    int col = warpN * 64 + nt * 8 + t4 * 2;
                    float v0 = acc[mt][nt][0], v1 = acc[mt][nt][1];
                    float v2 = acc[mt][nt][2], v3 = acc[mt][nt][3];
                    if (mat == 1) {
                        v0 = ((v0 > 20.f) ? v0 : log1pf(__expf(v0))) + EPSV;
                        v1 = ((v1 > 20.f) ? v1 : log1pf(__expf(v1))) + EPSV;
                        v2 = ((v2 > 20.f) ? v2 : log1pf(__expf(v2))) + EPSV;
                        v3 = ((v3 > 20.f) ? v3 : log1pf(__expf(v3))) + EPSV;
                    } else {
                        const float* bias = (mat == 0) ? b_fc : b_rob;
                        float b0 = bias[col], b1 = bias[col + 1];
                        v0 += b0; v1 += b1; v2 += b0; v3 += b1;
                    }
                    __half2 ha = __floats2half2_rn(v0, v1);
                    __half2 hb = __floats2half2_rn(v2, v3);
                    if (r0 < N_NODES) *(__half2*)(outp + (size_t)r0 * D + col) = ha;
                    if (r1 < N_NODES) *(__half2*)(outp + (size_t)r1 * D + col) = hb;
                }
            }
        }

        if (mat < 2) { cp_wait0(); __syncthreads(); }
    }
}

// ---------------- fused gather(fp16) + combine + LayerNorm (one warp per node) ----
__global__ __launch_bounds__(256) void k_final(const int* __restrict__ degree,
                                               const float* __restrict__ ln_g,
                                               const float* __restrict__ ln_b,
                                               float* __restrict__ out)
{
    int w = (blockIdx.x * blockDim.x + threadIdx.x) >> 5;
    int lane = threadIdx.x & 31;
    if (w >= N_NODES) return;
    size_t base = (size_t)w * D;

    int start = g_off[w] + g_bsum[w >> 9];
    int cnt = g_cnt[w];

    // each lane handles 4 consecutive cols: halves [lane*4, lane*4+4)
    float4 acc = make_float4(0.f, 0.f, 0.f, 0.f);
    int j = 0;
    for (; j + 8 <= cnt; j += 8) {
        int c[8];
        #pragma unroll
        for (int q = 0; q < 8; q++) c[q] = g_ecol[start + j + q];
        uint2 p[8];
        #pragma unroll
        for (int q = 0; q < 8; q++) p[q] = __ldg(((const uint2*)(g_hh + (size_t)c[q] * D)) + lane);
        #pragma unroll
        for (int q = 0; q < 8; q++) {
            float2 f01 = __half22float2(*(__half2*)&p[q].x);
            float2 f23 = __half22float2(*(__half2*)&p[q].y);
            acc.x += f01.x; acc.y += f01.y; acc.z += f23.x; acc.w += f23.y;
        }
    }
    for (; j < cnt; j++) {
        int c = g_ecol[start + j];
        uint2 p = __ldg(((const uint2*)(g_hh + (size_t)c * D)) + lane);
        float2 f01 = __half22float2(*(__half2*)&p.x);
        float2 f23 = __half22float2(*(__half2*)&p.y);
        acc.x += f01.x; acc.y += f01.y; acc.z += f23.x; acc.w += f23.y;
    }

    // self h / rate / gamma, all fp16
    uint2 ph = ((const uint2*)(g_hh + base))[lane];
    uint2 pr = ((const uint2*)(g_rateh + base))[lane];
    uint2 pg = ((const uint2*)(g_gammah + base))[lane];
    float2 h01 = __half22float2(*(__half2*)&ph.x);
    float2 h23 = __half22float2(*(__half2*)&ph.y);
    float2 r01 = __half22float2(*(__half2*)&pr.x);
    float2 r23 = __half22float2(*(__half2*)&pr.y);
    float2 q01 = __half22float2(*(__half2*)&pg.x);
    float2 q23 = __half22float2(*(__half2*)&pg.y);
    float hv[4] = {h01.x, h01.y, h23.x, h23.y};
    float rv[4] = {r01.x, r01.y, r23.x, r23.y};
    float gv[4] = {q01.x, q01.y, q23.x, q23.y};
    float fc = (float)cnt;
    float deg = (float)degree[w];

    float y[4];
    {
        const float* ap = (const float*)&acc;
        #pragma unroll
        for (int i = 0; i < 4; i++) {
            float agg_full = ap[i] + fc * hv[i];
            y[i] = (rv[i] * agg_full + gv[i]) / (1.0f + EPSV + rv[i] * deg);
        }
    }

    float s = y[0] + y[1] + y[2] + y[3];
    float s2 = y[0]*y[0] + y[1]*y[1] + y[2]*y[2] + y[3]*y[3];
    #pragma unroll
    for (int off = 16; off > 0; off >>= 1) {
        s  += __shfl_xor_sync(0xffffffffu, s,  off);
        s2 += __shfl_xor_sync(0xffffffffu, s2, off);
    }
    float mean = s * (1.0f / D);
    float var = s2 * (1.0f / D) - mean * mean;
    float rstd = rsqrtf(var + LN_EPSV);

    float4 lg = ((const float4*)ln_g)[lane];
    float4 lb = ((const float4*)ln_b)[lane];
    float4 o;
    o.x = (y[0] - mean) * rstd * lg.x + lb.x;
    o.y = (y[1] - mean) * rstd * lg.y + lb.y;
    o.z = (y[2] - mean) * rstd * lg.z + lb.z;
    o.w = (y[3] - mean) * rstd * lg.w + lb.w;
    ((float4*)(out + base))[lane] = o;
}

// ---------------- launch ----------------
extern "C" void kernel_launch(void* const* d_in, const int* in_sizes, int n_in,
                              void* d_out, int out_size) {
    const float* x      = (const float*)d_in[0];
    const int*   ei     = (const int*)  d_in[1];
    const int*   degree = (const int*)  d_in[2];
    const float* W_fc   = (const float*)d_in[3];
    const float* b_fc   = (const float*)d_in[4];
    const float* W_rate = (const float*)d_in[5];
    const float* W_rob  = (const float*)d_in[6];
    const float* b_rob  = (const float*)d_in[7];
    const float* ln_g   = (const float*)d_in[8];
    const float* ln_b   = (const float*)d_in[9];
    float* out = (float*)d_out;

    const int* row = ei;             // edge_index[0]
    const int* col = ei + E_EDGES;   // edge_index[1]

    // one-time setup (outside capture on the first/correctness call)
    static cudaStream_t sideStream = nullptr;
    static cudaEvent_t evRoot = nullptr, evSide = nullptr;
    if (!sideStream) {
        cudaStreamCreateWithFlags(&sideStream, cudaStreamNonBlocking);
        cudaEventCreateWithFlags(&evRoot, cudaEventDisableTiming);
        cudaEventCreateWithFlags(&evSide, cudaEventDisableTiming);
        cudaFuncSetAttribute(k_mm, cudaFuncAttributeMaxDynamicSharedMemorySize, SM_TOTAL);
    }

    // fork: CSR build on side stream, GEMM on main stream
    cudaEventRecord(evRoot, 0);
    cudaStreamWaitEvent(sideStream, evRoot, 0);

    // side stream: CSR build chain (latency-bound small kernels — hides under GEMM)
    k_zero<<<(N_NODES + 255) / 256, 256, 0, sideStream>>>();
    k_count<<<(E_EDGES + 255) / 256, 256, 0, sideStream>>>(row);
    k_scan1<<<NBLK, SCAN_B, 0, sideStream>>>();
    k_scan2<<<1, 256, 0, sideStream>>>();
    k_bin<<<(E_EDGES + 255) / 256, 256, 0, sideStream>>>(row, col);
    cudaEventRecord(evSide, sideStream);

    // main stream: weight convert + tensor-core GEMM
    k_wsplit<<<(3 * 128 * 32 + 255) / 256, 256>>>(W_fc, W_rate, W_rob);
    k_mm<<<MM_CTAS, MM_THREADS, SM_TOTAL>>>(x, b_fc, b_rob);

    // join, then fused gather + LayerNorm
    cudaStreamWaitEvent(0, evSide, 0);
    k_final<<<(int)(((size_t)N_NODES * 32 + 255) / 256), 256>>>(degree, ln_g, ln_b, out);
}

// round 17
// speedup vs baseline: 1.4817x; 1.0176x over previous
#include <cuda_runtime.h>
#include <cuda_fp16.h>
#include <math.h>
#include <cstdint>

#define N_NODES 100000
#define E_EDGES 800000
#define D 128
#define EPSV 1e-4f
#define LN_EPSV 1e-5f

#define SCAN_B 512
#define NBLK ((N_NODES + SCAN_B - 1) / SCAN_B)   // 196

#define TILE_M 256
#define MM_CTAS ((N_NODES + TILE_M - 1) / TILE_M)  // 391
#define MM_THREADS 512

// ---- scratch (device globals; no allocation allowed) ----
__device__ __half g_hh[(size_t)N_NODES * D];      // h in fp16
__device__ __half g_rateh[(size_t)N_NODES * D];   // softplus(x@W_rate)+eps in fp16
__device__ __half g_gammah[(size_t)N_NODES * D];  // x@W_rob + b_rob in fp16
__device__ int    g_cnt[N_NODES];
__device__ int    g_cur[N_NODES];
__device__ int    g_off[N_NODES];
__device__ int    g_bsum[NBLK];
__device__ int    g_ecol[E_EDGES];
// fp16 transposed weights: [mat(3)][n(128)][k(128)] halves (32KB per mat)
__device__ __half g_wh[3 * 128 * 128];

// ============================ helpers ============================
__device__ __forceinline__ uint32_t smem_u32(const void* p) {
    uint32_t a;
    asm("{ .reg .u64 t; cvta.to.shared.u64 t, %1; cvt.u32.u64 %0, t; }" : "=r"(a) : "l"(p));
    return a;
}

__device__ __forceinline__ void ldmatrix4(uint32_t* r, uint32_t addr) {
    asm volatile("ldmatrix.sync.aligned.m8n8.x4.shared.b16 {%0,%1,%2,%3}, [%4];"
                 : "=r"(r[0]), "=r"(r[1]), "=r"(r[2]), "=r"(r[3]) : "r"(addr));
}

__device__ __forceinline__ void mma16816(float* c, const uint32_t* a, uint32_t b0, uint32_t b1) {
    asm volatile("mma.sync.aligned.m16n8k16.row.col.f32.f16.f16.f32 "
                 "{%0,%1,%2,%3}, {%4,%5,%6,%7}, {%8,%9}, {%0,%1,%2,%3};"
                 : "+f"(c[0]), "+f"(c[1]), "+f"(c[2]), "+f"(c[3])
                 : "r"(a[0]), "r"(a[1]), "r"(a[2]), "r"(a[3]), "r"(b0), "r"(b1));
}

__device__ __forceinline__ void cp_async16(uint32_t saddr, const void* gaddr) {
    asm volatile("cp.async.cg.shared.global [%0], [%1], 16;" :: "r"(saddr), "l"(gaddr));
}
__device__ __forceinline__ void cp_commit() { asm volatile("cp.async.commit_group;"); }
__device__ __forceinline__ void cp_wait0()  { asm volatile("cp.async.wait_group 0;" ::: "memory"); }

// ============================ small kernels ============================
__global__ void k_zero() {
    int i = blockIdx.x * blockDim.x + threadIdx.x;
    if (i < N_NODES) g_cnt[i] = 0;
}

__global__ void k_count(const int* __restrict__ row) {
    int e = blockIdx.x * blockDim.x + threadIdx.x;
    if (e < E_EDGES) atomicAdd(&g_cnt[row[e]], 1);
}

__global__ __launch_bounds__(SCAN_B) void k_scan1() {
    __shared__ int wsum[SCAN_B / 32];
    int i = blockIdx.x * SCAN_B + threadIdx.x;
    int lane = threadIdx.x & 31, wid = threadIdx.x >> 5;
    int v = (i < N_NODES) ? g_cnt[i] : 0;
    if (i < N_NODES) g_cur[i] = 0;
    int s = v;
    #pragma unroll
    for (int o = 1; o < 32; o <<= 1) { int t = __shfl_up_sync(~0u, s, o); if (lane >= o) s += t; }
    if (lane == 31) wsum[wid] = s;
    __syncthreads();
    if (wid == 0) {
        int ws = (lane < SCAN_B / 32) ? wsum[lane] : 0;
        #pragma unroll
        for (int o = 1; o < SCAN_B / 32; o <<= 1) { int t = __shfl_up_sync(~0u, ws, o); if (lane >= o) ws += t; }
        if (lane < SCAN_B / 32) wsum[lane] = ws;
    }
    __syncthreads();
    int base = (wid > 0) ? wsum[wid - 1] : 0;
    if (i < N_NODES) g_off[i] = base + s - v;
    if (threadIdx.x == SCAN_B - 1) g_bsum[blockIdx.x] = base + s;
}

__global__ __launch_bounds__(256) void k_scan2() {
    __shared__ int wsum[8];
    int lane = threadIdx.x & 31, wid = threadIdx.x >> 5;
    int v = (threadIdx.x < NBLK) ? g_bsum[threadIdx.x] : 0;
    int s = v;
    #pragma unroll
    for (int o = 1; o < 32; o <<= 1) { int t = __shfl_up_sync(~0u, s, o); if (lane >= o) s += t; }
    if (lane == 31) wsum[wid] = s;
    __syncthreads();
    if (wid == 0) {
        int ws = (lane < 8) ? wsum[lane] : 0;
        #pragma unroll
        for (int o = 1; o < 8; o <<= 1) { int t = __shfl_up_sync(~0u, ws, o); if (lane >= o) ws += t; }
        if (lane < 8) wsum[lane] = ws;
    }
    __syncthreads();
    int base = (wid > 0) ? wsum[wid - 1] : 0;
    if (threadIdx.x < NBLK) g_bsum[threadIdx.x] = base + s - v;
}

__global__ __launch_bounds__(256) void k_bin(const int* __restrict__ row, const int* __restrict__ col) {
    int e = blockIdx.x * blockDim.x + threadIdx.x;
    if (e >= E_EDGES) return;
    int r = row[e];
    int pos = g_off[r] + g_bsum[r >> 9] + atomicAdd(&g_cur[r], 1);
    g_ecol[pos] = col[e];
}

// ---- pre-transpose W to fp16: g_wh[mat][n][k] ----
__global__ __launch_bounds__(256) void k_wsplit(const float* __restrict__ W_fc,
                                                const float* __restrict__ W_rate,
                                                const float* __restrict__ W_rob) {
    int t = blockIdx.x * blockDim.x + threadIdx.x;   // 3*128*32 = 12288
    if (t >= 3 * 128 * 32) return;
    int mat = t >> 12;
    int n = (t & 4095) >> 5;
    int k0 = (t & 31) << 2;
    const float* W = (mat == 0) ? W_fc : ((mat == 1) ? W_rate : W_rob);
    __half hi[4];
    #pragma unroll
    for (int i = 0; i < 4; i++)
        hi[i] = __float2half_rn(W[(size_t)(k0 + i) * D + n]);
    *(uint2*)(g_wh + ((size_t)mat << 14) + (n << 7) + k0) = *(uint2*)hi;
}

// ============================ mma.sync fused 3x GEMM ============================
// TILE_M=256, 512 threads (16 warps: 8 M-groups x 2 N-groups), 1 fp16 term.
// smem: x_hi [0,64K)  Wbuf0 [64K,96K)  Wbuf1 [96K,128K)  (double-buffered)
// fp16 [row][k] rows of 256B, 16B-unit swizzle: unit u -> u ^ (row & 7).
#define SM_XHI   0
#define SM_WB    65536
#define SM_TOTAL 131072

__global__ __launch_bounds__(MM_THREADS, 1) void k_mm(const float* __restrict__ x,
                                                      const float* __restrict__ b_fc,
                                                      const float* __restrict__ b_rob) {
    extern __shared__ char smem[];
    const uint32_t sbase = smem_u32(smem);
    const int tid = threadIdx.x;
    const int wid = tid >> 5;
    const int lane = tid & 31;
    const int m0 = blockIdx.x * TILE_M;
    const int warpM = wid & 7;     // rows 32*warpM .. +32
    const int warpN = wid >> 3;    // cols 64*warpN .. +64

    // ---- prefetch W[0] into buf0 (32KB = 2048 16B units, 4 per thread) ----
    {
        const char* wsrc = (const char*)g_wh;
        #pragma unroll
        for (int r = 0; r < 4; r++) {
            int idx = (r << 9) + tid;           // 0..2047
            int n = idx >> 4;
            int u = idx & 15;
            uint32_t dst = sbase + SM_WB + (uint32_t)(n * 256 + ((u ^ (n & 7)) << 4));
            cp_async16(dst, wsrc + (size_t)n * 256 + (u << 4));
        }
        cp_commit();
    }

    // ---- stage x tile as fp16 (256 rows x 128 k) ----
    #pragma unroll
    for (int r = 0; r < 16; r++) {
        int idx = (r << 9) + tid;           // 0..8191
        int m = idx >> 5;
        int kq = idx & 31;                  // float4 index; k0 = kq*4
        float4 v = make_float4(0.f, 0.f, 0.f, 0.f);
        if (m0 + m < N_NODES) v = *(const float4*)(x + (size_t)(m0 + m) * D + (kq << 2));
        uint2 hp;
        hp.x = __half_as_ushort(__float2half_rn(v.x)) | ((uint32_t)__half_as_ushort(__float2half_rn(v.y)) << 16);
        hp.y = __half_as_ushort(__float2half_rn(v.z)) | ((uint32_t)__half_as_ushort(__float2half_rn(v.w)) << 16);
        int u = kq >> 1;                    // 16B unit
        int off8 = (kq & 1) << 3;
        uint32_t so = (uint32_t)(m * 256 + ((u ^ (m & 7)) << 4) + off8);
        *(uint2*)(smem + SM_XHI + so) = hp;
    }
    cp_wait0();
    __syncthreads();

    // per-thread ldmatrix address components
    const int rowA_off = (lane & 7) + (((lane >> 3) & 1) << 3);
    const int dA = lane >> 4;
    const int nB_off = (lane & 7) + (((lane >> 4) & 1) << 3);
    const int dB = (lane >> 3) & 1;

    int rowA[2], s7A[2];
    #pragma unroll
    for (int mt = 0; mt < 2; mt++) {
        int rr = warpM * 32 + mt * 16 + rowA_off;
        rowA[mt] = rr * 256; s7A[mt] = rr & 7;
    }
    int rowB[4], s7B[4];
    #pragma unroll
    for (int nt2 = 0; nt2 < 4; nt2++) {
        int nn = warpN * 64 + nt2 * 16 + nB_off;
        rowB[nt2] = nn * 256; s7B[nt2] = nn & 7;
    }

    const int g4 = lane >> 2;      // C-frag row within tile
    const int t4 = lane & 3;       // C-frag col pair

    for (int mat = 0; mat < 3; mat++) {
        const int cur = mat & 1;
        float acc[2][8][4];
        #pragma unroll
        for (int mt = 0; mt < 2; mt++)
            #pragma unroll
            for (int nt = 0; nt < 8; nt++)
                #pragma unroll
                for (int i = 0; i < 4; i++) acc[mt][nt][i] = 0.f;

        const uint32_t abase = sbase + SM_XHI;
        const uint32_t bbase = sbase + SM_WB + (cur << 15);
        #pragma unroll 1
        for (int ks = 0; ks < 8; ks++) {
            uint32_t a[2][4];
            #pragma unroll
            for (int mt = 0; mt < 2; mt++) {
                int u = 2 * ks + dA;
                ldmatrix4(a[mt], abase + rowA[mt] + ((u ^ s7A[mt]) << 4));
            }
            uint32_t b[4][4];
            #pragma unroll
            for (int nt2 = 0; nt2 < 4; nt2++) {
                int u = 2 * ks + dB;
                ldmatrix4(b[nt2], bbase + rowB[nt2] + ((u ^ s7B[nt2]) << 4));
            }
            #pragma unroll
            for (int mt = 0; mt < 2; mt++)
                #pragma unroll
                for (int nt = 0; nt < 8; nt++)
                    mma16816(acc[mt][nt], a[mt], b[nt >> 1][(nt & 1) << 1], b[nt >> 1][((nt & 1) << 1) + 1]);
        }

        // prefetch next W into the OTHER buffer (safe: last read in mat-1,
        // fenced by that iteration's cp_wait0+__syncthreads). Overlaps epilogue.
        if (mat < 2) {
            const char* wsrc = (const char*)g_wh + ((size_t)(mat + 1) << 15);
            #pragma unroll
            for (int r = 0; r < 4; r++) {
                int idx = (r << 9) + tid;
                int n = idx >> 4;
                int u = idx & 15;
                uint32_t dst = sbase + SM_WB + ((cur ^ 1) << 15)
                             + (uint32_t)(n * 256 + ((u ^ (n & 7)) << 4));
                cp_async16(dst, wsrc + (size_t)n * 256 + (u << 4));
            }
            cp_commit();
        }

        // ---- epilogue for this mat: all outputs fp16 ----
        {
            __half* outp = (mat == 0) ? g_hh : ((mat == 1) ? g_rateh : g_gammah);
            #pragma unroll
            for (int mt = 0; mt < 2; mt++) {
                int r0 = m0 + warpM * 32 + mt * 16 + g4;
                int r1 = r0 + 8;
                #pragma unroll
                for (int nt = 0; nt < 8; nt++) {
                    int col = warpN * 64 + nt * 8 + t4 * 2;
                    float v0 = acc[mt][nt][0], v1 = acc[mt][nt][1];
                    float v2 = acc[mt][nt][2], v3 = acc[mt][nt][3];
                    if (mat == 1) {
                        v0 = ((v0 > 20.f) ? v0 : log1pf(__expf(v0))) + EPSV;
                        v1 = ((v1 > 20.f) ? v1 : log1pf(__expf(v1))) + EPSV;
                        v2 = ((v2 > 20.f) ? v2 : log1pf(__expf(v2))) + EPSV;
                        v3 = ((v3 > 20.f) ? v3 : log1pf(__expf(v3))) + EPSV;
                    } else {
                        const float* bias = (mat == 0) ? b_fc : b_rob;
                        float b0 = bias[col], b1 = bias[col + 1];
                        v0 += b0; v1 += b1; v2 += b0; v3 += b1;
                    }
                    __half2 ha = __floats2half2_rn(v0, v1);
                    __half2 hb = __floats2half2_rn(v2, v3);
                    if (r0 < N_NODES) *(__half2*)(outp + (size_t)r0 * D + col) = ha;
                    if (r1 < N_NODES) *(__half2*)(outp + (size_t)r1 * D + col) = hb;
                }
            }
        }

        if (mat < 2) { cp_wait0(); __syncthreads(); }
    }
}

// ------- fused gather(fp16) + combine + LayerNorm: 2 nodes per warp -------
// 16-lane groups; each lane covers 8 cols (uint4 = 16B of fp16 per row).
__global__ __launch_bounds__(256) void k_final(const int* __restrict__ degree,
                                               const float* __restrict__ ln_g,
                                               const float* __restrict__ ln_b,
                                               float* __restrict__ out)
{
    int warp = (blockIdx.x * blockDim.x + threadIdx.x) >> 5;
    int lane = threadIdx.x & 31;
    int half = lane >> 4;            // which node within the warp
    int sl = lane & 15;              // sub-lane within the 16-lane group
    int w = warp * 2 + half;
    if (w >= N_NODES) return;        // N_NODES even; whole warp in-range together
    size_t base = (size_t)w * D;

    int start = g_off[w] + g_bsum[w >> 9];
    int cnt = g_cnt[w];

    // accumulate 8 cols per lane
    float a[8] = {0.f, 0.f, 0.f, 0.f, 0.f, 0.f, 0.f, 0.f};
    int j = 0;
    for (; j + 4 <= cnt; j += 4) {
        int c0 = g_ecol[start + j + 0];
        int c1 = g_ecol[start + j + 1];
        int c2 = g_ecol[start + j + 2];
        int c3 = g_ecol[start + j + 3];
        uint4 p0 = __ldg(((const uint4*)(g_hh + (size_t)c0 * D)) + sl);
        uint4 p1 = __ldg(((const uint4*)(g_hh + (size_t)c1 * D)) + sl);
        uint4 p2 = __ldg(((const uint4*)(g_hh + (size_t)c2 * D)) + sl);
        uint4 p3 = __ldg(((const uint4*)(g_hh + (size_t)c3 * D)) + sl);
        const uint4* ps[4] = {&p0, &p1, &p2, &p3};
        #pragma unroll
        for (int q = 0; q < 4; q++) {
            const uint32_t* u = (const uint32_t*)ps[q];
            #pragma unroll
            for (int h2 = 0; h2 < 4; h2++) {
                float2 f = __half22float2(*(__half2*)&u[h2]);
                a[h2 * 2] += f.x; a[h2 * 2 + 1] += f.y;
            }
        }
    }
    for (; j < cnt; j++) {
        int c = g_ecol[start + j];
        uint4 p = __ldg(((const uint4*)(g_hh + (size_t)c * D)) + sl);
        const uint32_t* u = (const uint32_t*)&p;
        #pragma unroll
        for (int h2 = 0; h2 < 4; h2++) {
            float2 f = __half22float2(*(__half2*)&u[h2]);
            a[h2 * 2] += f.x; a[h2 * 2 + 1] += f.y;
        }
    }

    // self h / rate / gamma (fp16, 8 cols per lane)
    uint4 ph = ((const uint4*)(g_hh + base))[sl];
    uint4 pr = ((const uint4*)(g_rateh + base))[sl];
    uint4 pg = ((const uint4*)(g_gammah + base))[sl];
    float hv[8], rv[8], gv[8];
    {
        const uint32_t* uh = (const uint32_t*)&ph;
        const uint32_t* ur = (const uint32_t*)&pr;
        const uint32_t* ug = (const uint32_t*)&pg;
        #pragma unroll
        for (int h2 = 0; h2 < 4; h2++) {
            float2 fh = __half22float2(*(__half2*)&uh[h2]);
            float2 fr = __half22float2(*(__half2*)&ur[h2]);
            float2 fg = __half22float2(*(__half2*)&ug[h2]);
            hv[h2 * 2] = fh.x; hv[h2 * 2 + 1] = fh.y;
            rv[h2 * 2] = fr.x; rv[h2 * 2 + 1] = fr.y;
            gv[h2 * 2] = fg.x; gv[h2 * 2 + 1] = fg.y;
        }
    }
    float fc = (float)cnt;
    float deg = (float)degree[w];

    float y[8];
    float s = 0.f, s2 = 0.f;
    #pragma unroll
    for (int i = 0; i < 8; i++) {
        float agg_full = a[i] + fc * hv[i];
        float yi = (rv[i] * agg_full + gv[i]) / (1.0f + EPSV + rv[i] * deg);
        y[i] = yi;
        s += yi;
        s2 += yi * yi;
    }

    __syncwarp();
    #pragma unroll
    for (int off = 8; off > 0; off >>= 1) {
        s  += __shfl_xor_sync(0xffffffffu, s,  off);
        s2 += __shfl_xor_sync(0xffffffffu, s2, off);
    }
    float mean = s * (1.0f / D);
    float var = s2 * (1.0f / D) - mean * mean;
    float rstd = rsqrtf(var + LN_EPSV);

    float4 lg0 = ((const float4*)ln_g)[sl * 2];
    float4 lg1 = ((const float4*)ln_g)[sl * 2 + 1];
    float4 lb0 = ((const float4*)ln_b)[sl * 2];
    float4 lb1 = ((const float4*)ln_b)[sl * 2 + 1];
    float4 o0, o1;
    o0.x = (y[0] - mean) * rstd * lg0.x + lb0.x;
    o0.y = (y[1] - mean) * rstd * lg0.y + lb0.y;
    o0.z = (y[2] - mean) * rstd * lg0.z + lb0.z;
    o0.w = (y[3] - mean) * rstd * lg0.w + lb0.w;
    o1.x = (y[4] - mean) * rstd * lg1.x + lb1.x;
    o1.y = (y[5] - mean) * rstd * lg1.y + lb1.y;
    o1.z = (y[6] - mean) * rstd * lg1.z + lb1.z;
    o1.w = (y[7] - mean) * rstd * lg1.w + lb1.w;
    ((float4*)(out + base))[sl * 2] = o0;
    ((float4*)(out + base))[sl * 2 + 1] = o1;
}

// ---------------- launch ----------------
extern "C" void kernel_launch(void* const* d_in, const int* in_sizes, int n_in,
                              void* d_out, int out_size) {
    const float* x      = (const float*)d_in[0];
    const int*   ei     = (const int*)  d_in[1];
    const int*   degree = (const int*)  d_in[2];
    const float* W_fc   = (const float*)d_in[3];
    const float* b_fc   = (const float*)d_in[4];
    const float* W_rate = (const float*)d_in[5];
    const float* W_rob  = (const float*)d_in[6];
    const float* b_rob  = (const float*)d_in[7];
    const float* ln_g   = (const float*)d_in[8];
    const float* ln_b   = (const float*)d_in[9];
    float* out = (float*)d_out;

    const int* row = ei;             // edge_index[0]
    const int* col = ei + E_EDGES;   // edge_index[1]

    // one-time setup (outside capture on the first/correctness call)
    static cudaStream_t sideStream = nullptr;
    static cudaEvent_t evRoot = nullptr, evSide = nullptr;
    if (!sideStream) {
        cudaStreamCreateWithFlags(&sideStream, cudaStreamNonBlocking);
        cudaEventCreateWithFlags(&evRoot, cudaEventDisableTiming);
        cudaEventCreateWithFlags(&evSide, cudaEventDisableTiming);
        cudaFuncSetAttribute(k_mm, cudaFuncAttributeMaxDynamicSharedMemorySize, SM_TOTAL);
    }

    // fork: CSR build on side stream, GEMM on main stream
    cudaEventRecord(evRoot, 0);
    cudaStreamWaitEvent(sideStream, evRoot, 0);

    // side stream: CSR build chain (latency-bound small kernels — hides under GEMM)
    k_zero<<<(N_NODES + 255) / 256, 256, 0, sideStream>>>();
    k_count<<<(E_EDGES + 255) / 256, 256, 0, sideStream>>>(row);
    k_scan1<<<NBLK, SCAN_B, 0, sideStream>>>();
    k_scan2<<<1, 256, 0, sideStream>>>();
    k_bin<<<(E_EDGES + 255) / 256, 256, 0, sideStream>>>(row, col);
    cudaEventRecord(evSide, sideStream);

    // main stream: weight convert + tensor-core GEMM
    k_wsplit<<<(3 * 128 * 32 + 255) / 256, 256>>>(W_fc, W_rate, W_rob);
    k_mm<<<MM_CTAS, MM_THREADS, SM_TOTAL>>>(x, b_fc, b_rob);

    // join, then fused gather + LayerNorm (2 nodes per warp)
    cudaStreamWaitEvent(0, evSide, 0);
    k_final<<<(int)(((size_t)N_NODES / 2 * 32 + 255) / 256), 256>>>(degree, ln_g, ln_b, out);
}